// round 12
// baseline (speedup 1.0000x reference)
#include <cuda_runtime.h>
#include <math.h>
#include <stdint.h>

#define BZ   16
#define SEQ  512
#define DM   1024
#define NH   8
#define DH   128
#define SKM  513          // keys with memory token
#define N3   3072

// ---------------- static scratch (device globals; allocation-free) ----------
__device__ float g_mean[2][BZ][DM];
__device__ float g_gate[2][BZ][DM];
__device__ float g_K[3][BZ][SEQ + 1][DM];
__device__ float g_Q[3][BZ][SEQ][DM];
__device__ float g_V[3][BZ][SEQ + 1][DM];
__device__ float g_U[BZ][SEQ][DM];
__device__ uint32_t g_qA[BZ * SEQ * DM];     // tf32 bits of A operand [M][1024]
__device__ uint32_t g_qB[N3 * DM];           // tf32 bits of W^T operand [N][1024]

__device__ __forceinline__ uint32_t f2tf32(float x) {
    uint32_t r; asm("cvt.rna.tf32.f32 %0, %1;" : "=r"(r) : "f"(x)); return r;
}
__device__ __forceinline__ void mma_tf32(float* c, uint32_t a0, uint32_t a1,
                                         uint32_t a2, uint32_t a3,
                                         uint32_t b0, uint32_t b1) {
    asm volatile(
        "mma.sync.aligned.m16n8k8.row.col.f32.tf32.tf32.f32 "
        "{%0,%1,%2,%3}, {%4,%5,%6,%7}, {%8,%9}, {%0,%1,%2,%3};"
        : "+f"(c[0]), "+f"(c[1]), "+f"(c[2]), "+f"(c[3])
        : "r"(a0), "r"(a1), "r"(a2), "r"(a3), "r"(b0), "r"(b1));
}
__device__ __forceinline__ void ldsm4(uint32_t& r0, uint32_t& r1, uint32_t& r2,
                                      uint32_t& r3, uint32_t addr) {
    asm volatile("ldmatrix.sync.aligned.m8n8.x4.shared.b16 {%0,%1,%2,%3}, [%4];"
                 : "=r"(r0), "=r"(r1), "=r"(r2), "=r"(r3) : "r"(addr));
}
__device__ __forceinline__ uint32_t cvta_sm(const void* p) {
    uint32_t a;
    asm("{ .reg .u64 t; cvta.to.shared.u64 t, %1; cvt.u32.u64 %0, t; }" : "=r"(a) : "l"(p));
    return a;
}

// ---------------- tf32 quantization pre-pass (A path) ----------------
// MODE 0: o = tf32(relu(x));  1: o = tf32(x + g_U)
__global__ void quant_kernel(const float* __restrict__ x, uint32_t* __restrict__ o,
                             int n, int mode) {
    int i = (blockIdx.x * 256 + threadIdx.x) * 4;
    if (i >= n) return;
    float4 v = *(const float4*)(x + i);
    if (mode == 0) {
        v.x = fmaxf(v.x, 0.f); v.y = fmaxf(v.y, 0.f);
        v.z = fmaxf(v.z, 0.f); v.w = fmaxf(v.w, 0.f);
    } else {
        float4 u = *(const float4*)(&g_U[0][0][0] + i);
        v.x += u.x; v.y += u.y; v.z += u.z; v.w += u.w;
    }
    *(uint4*)(o + i) = make_uint4(f2tf32(v.x), f2tf32(v.y), f2tf32(v.z), f2tf32(v.w));
}

// ---------------- transposed quant for W: [1024][N] -> tf32 bits [N][1024] ----
__global__ void quantT_kernel(const float* __restrict__ w, uint32_t* __restrict__ o, int N) {
    __shared__ uint32_t t[32][33];
    int n0 = blockIdx.x * 32, k0 = blockIdx.y * 32;
    int tx = threadIdx.x, ty = threadIdx.y;
#pragma unroll
    for (int r = 0; r < 4; r++) {
        int k = ty + r * 8;
        t[tx][k] = f2tf32(w[(size_t)(k0 + k) * N + n0 + tx]);
    }
    __syncthreads();
#pragma unroll
    for (int r = 0; r < 4; r++) {
        int n = ty + r * 8;
        o[(size_t)(n0 + n) * DM + k0 + tx] = t[n][tx];
    }
}

// ============ cp.async 3-stage tf32 GEMM + ldmatrix fragments ==============
// A tile [128 m][32 k] and B tile [128 n][32 k], both padded stride 36 words.
// MODE 0: D = (qA @ qB^T + bias) * mask, optional gate, scatter to g_K/Q/V
// MODE 1: D = (qA @ qB^T + bias) -> outp
#define GT_WORDS (128 * 36)
#define GT_BYTES (GT_WORDS * 4)
#define ST_WORDS (2 * GT_WORDS)
#define ST_BYTES (ST_WORDS * 4)
#define GEMM_SMEM (3 * ST_BYTES)

template <int MODE>
__global__ void __launch_bounds__(256, 2) gemm_cp(
    const float* __restrict__ bias, const float* __restrict__ mask,
    float* __restrict__ outp, int mod, int gated, int rowoff) {
    extern __shared__ uint32_t sm[];
    uint32_t sbase = cvta_sm(sm);

    int tid = threadIdx.x;
    int wid = tid >> 5, lane = tid & 31;
    int g = lane >> 2, u = lane & 3;
    int wm = (wid >> 2) * 64;
    int wn = (wid & 3) * 32;
    int mtile = blockIdx.y * 128;
    int ntile = blockIdx.x * 128;

    // ldmatrix lane offset (identical for A and B tiles: same layout)
    int mi = lane >> 3, r8 = lane & 7;
    uint32_t lm_off = (uint32_t)(((mi & 1) * 8 + r8) * 36 + (mi >> 1) * 4) * 4;

    // cp.async per-thread coords: idx = tid + l*256 -> row=idx>>3, c4=(idx&7)*4
    int rows_[4], c4s_[4];
    uint32_t aoff[4], boff[4];
#pragma unroll
    for (int l = 0; l < 4; l++) {
        int idx = tid + l * 256;
        rows_[l] = idx >> 3;
        c4s_[l] = (idx & 7) * 4;
        aoff[l] = (uint32_t)(rows_[l] * 36 + c4s_[l]) * 4;
        boff[l] = aoff[l] + GT_BYTES;
    }

    float acc[4][4][4];
#pragma unroll
    for (int i = 0; i < 4; i++)
#pragma unroll
        for (int j = 0; j < 4; j++)
#pragma unroll
            for (int e = 0; e < 4; e++) acc[i][j][e] = 0.f;

    const uint32_t* Aq = g_qA;
    const uint32_t* Bq = g_qB;

#define ISSUE_TILE(KT, S) do {                                                     \
    if ((KT) < 32) {                                                               \
        int _k0 = (KT) * 32;                                                       \
        uint32_t _sb = sbase + (uint32_t)(S) * ST_BYTES;                           \
        _Pragma("unroll")                                                          \
        for (int _l = 0; _l < 4; _l++) {                                           \
            const uint32_t* _ga = Aq + (size_t)(mtile + rows_[_l]) * DM + _k0 + c4s_[_l]; \
            asm volatile("cp.async.cg.shared.global [%0], [%1], 16;"               \
                         :: "r"(_sb + aoff[_l]), "l"(_ga) : "memory");             \
            const uint32_t* _gb = Bq + (size_t)(ntile + rows_[_l]) * DM + _k0 + c4s_[_l]; \
            asm volatile("cp.async.cg.shared.global [%0], [%1], 16;"               \
                         :: "r"(_sb + boff[_l]), "l"(_gb) : "memory");             \
        }                                                                          \
    }                                                                              \
    asm volatile("cp.async.commit_group;" ::: "memory");                           \
} while (0)

    ISSUE_TILE(0, 0);
    ISSUE_TILE(1, 1);
    asm volatile("cp.async.wait_group 1;" ::: "memory");
    __syncthreads();

    int cur = 0;
    for (int kt = 0; kt < 32; kt++) {
        uint32_t stage = sbase + (uint32_t)cur * ST_BYTES;
        uint32_t aS = stage + (uint32_t)(wm * 36) * 4 + lm_off;
        uint32_t bS = stage + GT_BYTES + (uint32_t)(wn * 36) * 4 + lm_off;

#pragma unroll
        for (int ks = 0; ks < 4; ks++) {
            uint32_t kb = (uint32_t)(ks * 8) * 4;
            uint32_t af[4][4], bf[4][2];
#pragma unroll
            for (int i = 0; i < 4; i++)
                ldsm4(af[i][0], af[i][1], af[i][2], af[i][3],
                      aS + (uint32_t)(i * 16 * 36) * 4 + kb);
#pragma unroll
            for (int jp = 0; jp < 2; jp++)
                ldsm4(bf[2 * jp][0], bf[2 * jp + 1][0], bf[2 * jp][1], bf[2 * jp + 1][1],
                      bS + (uint32_t)(jp * 16 * 36) * 4 + kb);
#pragma unroll
            for (int i = 0; i < 4; i++)
#pragma unroll
                for (int j = 0; j < 4; j++)
                    mma_tf32(acc[i][j], af[i][0], af[i][1], af[i][2], af[i][3],
                             bf[j][0], bf[j][1]);
        }

        int nxt = cur + 2; if (nxt >= 3) nxt -= 3;
        ISSUE_TILE(kt + 2, nxt);
        asm volatile("cp.async.wait_group 1;" ::: "memory");
        __syncthreads();
        cur = cur + 1; if (cur == 3) cur = 0;
    }

    // ---- epilogue ----
    int part = ntile >> 10;
#pragma unroll
    for (int i = 0; i < 4; i++) {
        int r0 = mtile + wm + i * 16 + g;
        int r1 = r0 + 8;
#pragma unroll
        for (int j = 0; j < 4; j++) {
            int col = ntile + wn + j * 8 + u * 2;
            if (MODE == 1) {
                float b0 = bias[col], b1 = bias[col + 1];
                *(float2*)(outp + (size_t)r0 * DM + col) =
                    make_float2(acc[i][j][0] + b0, acc[i][j][1] + b1);
                *(float2*)(outp + (size_t)r1 * DM + col) =
                    make_float2(acc[i][j][2] + b0, acc[i][j][3] + b1);
            } else {
                float b0 = bias[col], b1 = bias[col + 1];
                int d0 = col & 1023;
#pragma unroll
                for (int h = 0; h < 2; h++) {
                    int r = h ? r1 : r0;
                    int b = r >> 9, si = r & 511;
                    float mk = mask[r];
                    float v0 = (acc[i][j][h * 2 + 0] + b0) * mk;
                    float v1 = (acc[i][j][h * 2 + 1] + b1) * mk;
                    if (gated && part < 2) {
                        v0 *= g_gate[mod][b][d0];
                        v1 *= g_gate[mod][b][d0 + 1];
                    }
                    float* dst;
                    if (part == 0)      dst = &g_K[mod][b][rowoff + si][d0];
                    else if (part == 1) dst = &g_Q[mod][b][si][d0];
                    else                dst = &g_V[mod][b][rowoff + si][d0];
                    *(float2*)dst = make_float2(v0, v1);
                }
            }
        }
    }
}

// ================= fused flash attention (tf32 mma) =========================
#define FA_LDQ 132
#define FA_LDP 68
#define FA_SMEM (3 * 64 * FA_LDQ * 4 + 64 * FA_LDP * 4 + (64 * 6 + 128) * 4)

__global__ void __launch_bounds__(256) flash_attn(
    const float* __restrict__ mask, int mod, int Sk, int hasmem) {
    extern __shared__ char smraw[];
    uint32_t* Qs = (uint32_t*)smraw;
    uint32_t* Ks = Qs + 64 * FA_LDQ;
    uint32_t* Vs = Ks + 64 * FA_LDQ;
    uint32_t* Ps = Vs + 64 * FA_LDQ;
    float* m_s  = (float*)(Ps + 64 * FA_LDP);
    float* l_s  = m_s + 64;
    float* al_s = l_s + 64;
    float* red  = al_s + 64;     // [2][64]
    float* kms  = red + 128;

    int tid = threadIdx.x;
    int wid = tid >> 5, lane = tid & 31;
    int g = lane >> 2, u = lane & 3;
    int wm = (wid >> 1) * 16;
    int wns = (wid & 1) * 32;
    int wno = (wid & 1) * 64;
    int bh = blockIdx.y;
    int b = bh >> 3, h = bh & 7;
    int qt0 = blockIdx.x * 64;

    const float* Qg = &g_Q[mod][b][0][h * DH];
    const float* Kg = &g_K[mod][b][0][h * DH];
    const float* Vg = &g_V[mod][b][0][h * DH];

#pragma unroll
    for (int l = 0; l < 8; l++) {
        int idx = tid + l * 256;
        int row = idx >> 5;
        int c4 = (idx & 31) * 4;
        float4 v = *(const float4*)(Qg + (size_t)(qt0 + row) * DM + c4);
        uint32_t* d = &Qs[row * FA_LDQ + c4];
        d[0] = f2tf32(v.x); d[1] = f2tf32(v.y); d[2] = f2tf32(v.z); d[3] = f2tf32(v.w);
    }
    if (tid < 64) { m_s[tid] = -3.4e38f; l_s[tid] = 0.f; }

    float acc_o[8][4];
#pragma unroll
    for (int j = 0; j < 8; j++)
#pragma unroll
        for (int e = 0; e < 4; e++) acc_o[j][e] = 0.f;

    const float scl = 0.08838834764831845f;   // 1/sqrt(128)
    int r0l = wm + g, r1l = wm + g + 8;
    int nt = (Sk + 63) >> 6;

    for (int t = 0; t < nt; t++) {
        int kt0 = t * 64;
        __syncthreads();
#pragma unroll
        for (int l = 0; l < 8; l++) {
            int idx = tid + l * 256;
            int row = idx >> 5;
            int c4 = (idx & 31) * 4;
            int key = kt0 + row;
            float4 kv = make_float4(0.f, 0.f, 0.f, 0.f);
            float4 vv = make_float4(0.f, 0.f, 0.f, 0.f);
            if (key < Sk) {
                kv = *(const float4*)(Kg + (size_t)key * DM + c4);
                vv = *(const float4*)(Vg + (size_t)key * DM + c4);
            }
            uint32_t* dk = &Ks[row * FA_LDQ + c4];
            dk[0] = f2tf32(kv.x); dk[1] = f2tf32(kv.y); dk[2] = f2tf32(kv.z); dk[3] = f2tf32(kv.w);
            uint32_t* dv = &Vs[row * FA_LDQ + c4];
            dv[0] = f2tf32(vv.x); dv[1] = f2tf32(vv.y); dv[2] = f2tf32(vv.z); dv[3] = f2tf32(vv.w);
        }
        if (tid < 64) {
            int key = kt0 + tid;
            float km = 0.f;
            if (key < Sk)
                km = hasmem ? ((key == 0) ? 1.f : mask[b * SEQ + key - 1])
                            : mask[b * SEQ + key];
            kms[tid] = km;
        }
        __syncthreads();

        float s[4][4];
#pragma unroll
        for (int j = 0; j < 4; j++)
#pragma unroll
            for (int e = 0; e < 4; e++) s[j][e] = 0.f;
#pragma unroll
        for (int kk = 0; kk < 16; kk++) {
            int k8 = kk * 8;
            uint32_t a0 = Qs[r0l * FA_LDQ + k8 + u];
            uint32_t a1 = Qs[r1l * FA_LDQ + k8 + u];
            uint32_t a2 = Qs[r0l * FA_LDQ + k8 + u + 4];
            uint32_t a3 = Qs[r1l * FA_LDQ + k8 + u + 4];
#pragma unroll
            for (int j = 0; j < 4; j++) {
                int n = wns + j * 8 + g;
                uint32_t b0 = Ks[n * FA_LDQ + k8 + u];
                uint32_t b1 = Ks[n * FA_LDQ + k8 + u + 4];
                mma_tf32(s[j], a0, a1, a2, a3, b0, b1);
            }
        }
        float rm0 = -3.4e38f, rm1 = -3.4e38f;
#pragma unroll
        for (int j = 0; j < 4; j++) {
            int col = wns + j * 8 + u * 2;
            float k0m = kms[col], k1m = kms[col + 1];
            s[j][0] = (k0m != 0.f ? s[j][0] : -1e9f) * scl;
            s[j][1] = (k1m != 0.f ? s[j][1] : -1e9f) * scl;
            s[j][2] = (k0m != 0.f ? s[j][2] : -1e9f) * scl;
            s[j][3] = (k1m != 0.f ? s[j][3] : -1e9f) * scl;
            rm0 = fmaxf(rm0, fmaxf(s[j][0], s[j][1]));
            rm1 = fmaxf(rm1, fmaxf(s[j][2], s[j][3]));
        }
        rm0 = fmaxf(rm0, __shfl_xor_sync(0xffffffffu, rm0, 1));
        rm0 = fmaxf(rm0, __shfl_xor_sync(0xffffffffu, rm0, 2));
        rm1 = fmaxf(rm1, __shfl_xor_sync(0xffffffffu, rm1, 1));
        rm1 = fmaxf(rm1, __shfl_xor_sync(0xffffffffu, rm1, 2));
        if (u == 0) {
            red[(wid & 1) * 64 + r0l] = rm0;
            red[(wid & 1) * 64 + r1l] = rm1;
        }
        __syncthreads();
        if ((wid & 1) == 0 && u == 0) {
#pragma unroll
            for (int hh = 0; hh < 2; hh++) {
                int r = hh ? r1l : r0l;
                float tm = fmaxf(red[r], red[64 + r]);
                float mo = m_s[r];
                float mn = fmaxf(mo, tm);
                al_s[r] = expf(mo - mn);
                m_s[r] = mn;
            }
        }
        __syncthreads();
        float mn0 = m_s[r0l], mn1 = m_s[r1l];
        float rs0 = 0.f, rs1 = 0.f;
#pragma unroll
        for (int j = 0; j < 4; j++) {
            int col = wns + j * 8 + u * 2;
            float p0 = expf(s[j][0] - mn0);
            float p1 = expf(s[j][1] - mn0);
            float p2 = expf(s[j][2] - mn1);
            float p3 = expf(s[j][3] - mn1);
            rs0 += p0 + p1; rs1 += p2 + p3;
            Ps[r0l * FA_LDP + col]     = f2tf32(p0);
            Ps[r0l * FA_LDP + col + 1] = f2tf32(p1);
            Ps[r1l * FA_LDP + col]     = f2tf32(p2);
            Ps[r1l * FA_LDP + col + 1] = f2tf32(p3);
        }
        rs0 += __shfl_xor_sync(0xffffffffu, rs0, 1);
        rs0 += __shfl_xor_sync(0xffffffffu, rs0, 2);
        rs1 += __shfl_xor_sync(0xffffffffu, rs1, 1);
        rs1 += __shfl_xor_sync(0xffffffffu, rs1, 2);
        if (u == 0) {
            red[(wid & 1) * 64 + r0l] = rs0;
            red[(wid & 1) * 64 + r1l] = rs1;
        }
        __syncthreads();
        if ((wid & 1) == 0 && u == 0) {
            l_s[r0l] = l_s[r0l] * al_s[r0l] + red[r0l] + red[64 + r0l];
            l_s[r1l] = l_s[r1l] * al_s[r1l] + red[r1l] + red[64 + r1l];
        }
        float a0s = al_s[r0l], a1s = al_s[r1l];
#pragma unroll
        for (int j = 0; j < 8; j++) {
            acc_o[j][0] *= a0s; acc_o[j][1] *= a0s;
            acc_o[j][2] *= a1s; acc_o[j][3] *= a1s;
        }
#pragma unroll
        for (int ks = 0; ks < 8; ks++) {
            int k8 = ks * 8;
            uint32_t a0 = Ps[r0l * FA_LDP + k8 + u];
            uint32_t a1 = Ps[r1l * FA_LDP + k8 + u];
            uint32_t a2 = Ps[r0l * FA_LDP + k8 + u + 4];
            uint32_t a3 = Ps[r1l * FA_LDP + k8 + u + 4];
#pragma unroll
            for (int j = 0; j < 8; j++) {
                int n = wno + j * 8 + g;
                uint32_t b0 = Vs[(k8 + u) * FA_LDQ + n];
                uint32_t b1 = Vs[(k8 + u + 4) * FA_LDQ + n];
                mma_tf32(acc_o[j], a0, a1, a2, a3, b0, b1);
            }
        }
    }
    __syncthreads();
    float inv0 = 1.f / l_s[r0l];
    float inv1 = 1.f / l_s[r1l];
    int qr0 = qt0 + r0l, qr1 = qt0 + r1l;
#pragma unroll
    for (int j = 0; j < 8; j++) {
        int col = h * DH + wno + j * 8 + u * 2;
        *(float2*)&g_U[b][qr0][col] =
            make_float2(acc_o[j][0] * inv0, acc_o[j][1] * inv0);
        *(float2*)&g_U[b][qr1][col] =
            make_float2(acc_o[j][2] * inv1, acc_o[j][3] * inv1);
    }
}

// ---------------- masked mean (parallel over d-chunks) ----------------
__global__ void mean_kernel(const float* __restrict__ x, const float* __restrict__ mask, int slot) {
    int b = blockIdx.y;
    int d = blockIdx.x * 128 + threadIdx.x;
    __shared__ float sm[SEQ];
    __shared__ float smsum;
    for (int i = threadIdx.x; i < SEQ; i += 128) sm[i] = mask[b * SEQ + i];
    __syncthreads();
    if (threadIdx.x == 0) {
        float s = 0.f;
        for (int i = 0; i < SEQ; i++) s += sm[i];
        smsum = s;
    }
    __syncthreads();
    float inv = 1.f / smsum;
    float acc = 0.f;
    for (int i = 0; i < SEQ; i++) acc += x[(size_t)(b * SEQ + i) * DM + d] * sm[i];
    g_mean[slot][b][d] = acc * inv;
}

// ---------------- gate = 1 + sigmoid(relu(mean) @ w + b) ----------------
__global__ void gate_kernel(int mean_slot, const float* __restrict__ w,
                            const float* __restrict__ bias, int gate_slot) {
    int b = blockIdx.y;
    int d = blockIdx.x * 128 + threadIdx.x;
    __shared__ float sm[DM];
    for (int k = threadIdx.x; k < DM; k += 128) sm[k] = fmaxf(g_mean[mean_slot][b][k], 0.f);
    __syncthreads();
    float acc = bias[d];
    for (int k = 0; k < DM; k++) acc = fmaf(sm[k], w[k * DM + d], acc);
    g_gate[gate_slot][b][d] = 1.f + 1.f / (1.f + expf(-acc));
}

// ---------------- memory tokens ----------------
__global__ void memtok_kernel(const float* __restrict__ mvk, const float* __restrict__ mvv,
                              const float* __restrict__ mck, const float* __restrict__ mcv) {
    int b = blockIdx.y;
    int d = blockIdx.x * 128 + threadIdx.x;
    float gv = g_gate[0][b][d];
    g_K[0][b][0][d] = 32.f * mvk[d] * gv;
    g_V[0][b][0][d] = mvv[d];
    g_K[2][b][0][d] = 32.f * mck[d];
    g_V[2][b][0][d] = mcv[d];
}

// ---------------- orchestration ----------------
extern "C" void kernel_launch(void* const* d_in, const int* in_sizes, int n_in,
                              void* d_out, int out_size) {
    const float* v      = (const float*)d_in[0];
    const float* q      = (const float*)d_in[1];
    const float* c      = (const float*)d_in[2];
    const float* v_mask = (const float*)d_in[3];
    const float* q_mask = (const float*)d_in[4];
    const float* c_mask = (const float*)d_in[5];
    const float* v4q_w  = (const float*)d_in[6];
    const float* v4q_b  = (const float*)d_in[7];
    const float* q4v_w  = (const float*)d_in[8];
    const float* q4v_b  = (const float*)d_in[9];
    const float* v_lin_w = (const float*)d_in[10];
    const float* v_lin_b = (const float*)d_in[11];
    const float* q_lin_w = (const float*)d_in[12];
    const float* q_lin_b = (const float*)d_in[13];
    const float* c_lin_w = (const float*)d_in[14];
    const float* c_lin_b = (const float*)d_in[15];
    const float* m_v_k  = (const float*)d_in[16];
    const float* m_v_v  = (const float*)d_in[17];
    const float* m_c_k  = (const float*)d_in[18];
    const float* m_c_v  = (const float*)d_in[19];
    const float* v_out_w = (const float*)d_in[20];
    const float* v_out_b = (const float*)d_in[21];
    const float* q_out_w = (const float*)d_in[22];
    const float* q_out_b = (const float*)d_in[23];
    const float* c_out_w = (const float*)d_in[24];
    const float* c_out_b = (const float*)d_in[25];
    float* out = (float*)d_out;

    static int attr_set = 0;
    if (!attr_set) {
        cudaFuncSetAttribute(flash_attn, cudaFuncAttributeMaxDynamicSharedMemorySize, FA_SMEM);
        cudaFuncSetAttribute(gemm_cp<0>, cudaFuncAttributeMaxDynamicSharedMemorySize, GEMM_SMEM);
        cudaFuncSetAttribute(gemm_cp<1>, cudaFuncAttributeMaxDynamicSharedMemorySize, GEMM_SMEM);
        attr_set = 1;
    }

    const int NA = BZ * SEQ * DM;       // 8388608

    // 1) masked means
    mean_kernel<<<dim3(8, BZ), 128>>>(v, v_mask, 0);
    mean_kernel<<<dim3(8, BZ), 128>>>(q, q_mask, 1);

    // 2) gates
    gate_kernel<<<dim3(8, BZ), 128>>>(1, q4v_w, q4v_b, 0);
    gate_kernel<<<dim3(8, BZ), 128>>>(0, v4q_w, v4q_b, 1);

    // 3) memory tokens
    memtok_kernel<<<dim3(8, BZ), 128>>>(m_v_k, m_v_v, m_c_k, m_c_v);

    // 4) trans GEMMs: quantize (A straight, W transposed) then cp.async GEMM
    const float* xin[3]  = {v, q, c};
    const float* lw[3]   = {v_lin_w, q_lin_w, c_lin_w};
    const float* lb[3]   = {v_lin_b, q_lin_b, c_lin_b};
    const float* masks[3] = {v_mask, q_mask, c_mask};
    const int    gatedv[3] = {1, 1, 0};
    const int    rowoffv[3] = {1, 0, 1};

    uint32_t* qA = nullptr; cudaGetSymbolAddress((void**)&qA, g_qA);
    uint32_t* qB = nullptr; cudaGetSymbolAddress((void**)&qB, g_qB);

    dim3 tg(N3 / 128, (BZ * SEQ) / 128);
    for (int m = 0; m < 3; m++) {
        quant_kernel<<<NA / 1024, 256>>>(xin[m], qA, NA, 0);
        quantT_kernel<<<dim3(N3 / 32, DM / 32), dim3(32, 8)>>>(lw[m], qB, N3);
        gemm_cp<0><<<tg, 256, GEMM_SMEM>>>(lb[m], masks[m], nullptr, m,
                                           gatedv[m], rowoffv[m]);
    }

    // 5) per-modality fused flash attention + out projection
    const float* ows[3] = {v_out_w, q_out_w, c_out_w};
    const float* obs[3] = {v_out_b, q_out_b, c_out_b};
    const int    sks[3] = {SKM, SEQ, SKM};
    const int    hasm[3] = {1, 0, 1};

    dim3 og(DM / 128, (BZ * SEQ) / 128);
    for (int m = 0; m < 3; m++) {
        flash_attn<<<dim3(SEQ / 64, BZ * NH), 256, FA_SMEM>>>(masks[m], m, sks[m], hasm[m]);
        quant_kernel<<<NA / 1024, 256>>>(xin[m], qA, NA, 1);       // x + U
        quantT_kernel<<<dim3(DM / 32, DM / 32), dim3(32, 8)>>>(ows[m], qB, DM);
        gemm_cp<1><<<og, 256, GEMM_SMEM>>>(obs[m], nullptr,
                                           out + (size_t)m * BZ * SEQ * DM,
                                           0, 0, 0);
    }
}

// round 13
// speedup vs baseline: 1.4590x; 1.4590x over previous
#include <cuda_runtime.h>
#include <cuda_fp16.h>
#include <math.h>
#include <stdint.h>

#define BZ   16
#define SEQ  512
#define DM   1024
#define NH   8
#define DH   128
#define SKM  513          // keys with memory token
#define N3   3072

// ---------------- static scratch (device globals; allocation-free) ----------
__device__ float g_mean[2][BZ][DM];
__device__ float g_gate[2][BZ][DM];
__device__ float g_K[3][BZ][SEQ + 1][DM];
__device__ float g_Q[3][BZ][SEQ][DM];
__device__ float g_V[3][BZ][SEQ + 1][DM];
__device__ float g_U[BZ][SEQ][DM];
__device__ uint32_t g_qA[BZ * SEQ * DM / 2];   // fp16 pairs of A operand [M][1024]
__device__ uint32_t g_qB[N3 * DM / 2];         // fp16 pairs of W^T operand [N][1024]

__device__ __forceinline__ uint32_t f2tf32(float x) {
    uint32_t r; asm("cvt.rna.tf32.f32 %0, %1;" : "=r"(r) : "f"(x)); return r;
}
__device__ __forceinline__ void mma_tf32(float* c, uint32_t a0, uint32_t a1,
                                         uint32_t a2, uint32_t a3,
                                         uint32_t b0, uint32_t b1) {
    asm volatile(
        "mma.sync.aligned.m16n8k8.row.col.f32.tf32.tf32.f32 "
        "{%0,%1,%2,%3}, {%4,%5,%6,%7}, {%8,%9}, {%0,%1,%2,%3};"
        : "+f"(c[0]), "+f"(c[1]), "+f"(c[2]), "+f"(c[3])
        : "r"(a0), "r"(a1), "r"(a2), "r"(a3), "r"(b0), "r"(b1));
}
__device__ __forceinline__ void mma_f16(float* c, uint32_t a0, uint32_t a1,
                                        uint32_t a2, uint32_t a3,
                                        uint32_t b0, uint32_t b1) {
    asm volatile(
        "mma.sync.aligned.m16n8k16.row.col.f32.f16.f16.f32 "
        "{%0,%1,%2,%3}, {%4,%5,%6,%7}, {%8,%9}, {%0,%1,%2,%3};"
        : "+f"(c[0]), "+f"(c[1]), "+f"(c[2]), "+f"(c[3])
        : "r"(a0), "r"(a1), "r"(a2), "r"(a3), "r"(b0), "r"(b1));
}
__device__ __forceinline__ void ldsm4(uint32_t& r0, uint32_t& r1, uint32_t& r2,
                                      uint32_t& r3, uint32_t addr) {
    asm volatile("ldmatrix.sync.aligned.m8n8.x4.shared.b16 {%0,%1,%2,%3}, [%4];"
                 : "=r"(r0), "=r"(r1), "=r"(r2), "=r"(r3) : "r"(addr));
}
__device__ __forceinline__ uint32_t cvta_sm(const void* p) {
    uint32_t a;
    asm("{ .reg .u64 t; cvta.to.shared.u64 t, %1; cvt.u32.u64 %0, t; }" : "=r"(a) : "l"(p));
    return a;
}
__device__ __forceinline__ uint32_t packh2(float a, float b) {
    __half2 h = __floats2half2_rn(a, b);
    return *(uint32_t*)&h;
}

// ---------------- fp16 quantization pre-pass (A path) ----------------
// MODE 0: o = h(relu(x));  1: o = h(x + g_U)
__global__ void quant_kernel(const float* __restrict__ x, uint32_t* __restrict__ o,
                             int n, int mode) {
    int i = (blockIdx.x * 256 + threadIdx.x) * 4;
    if (i >= n) return;
    float4 v = *(const float4*)(x + i);
    if (mode == 0) {
        v.x = fmaxf(v.x, 0.f); v.y = fmaxf(v.y, 0.f);
        v.z = fmaxf(v.z, 0.f); v.w = fmaxf(v.w, 0.f);
    } else {
        float4 u = *(const float4*)(&g_U[0][0][0] + i);
        v.x += u.x; v.y += u.y; v.z += u.z; v.w += u.w;
    }
    *(uint2*)(o + i / 2) = make_uint2(packh2(v.x, v.y), packh2(v.z, v.w));
}

// ------- transposed quant for W: [1024][N] fp32 -> fp16 pairs [N][1024] -----
__global__ void quantT_kernel(const float* __restrict__ w, uint32_t* __restrict__ o, int N) {
    __shared__ float t[32][33];
    int n0 = blockIdx.x * 32, k0 = blockIdx.y * 32;
    int tx = threadIdx.x, ty = threadIdx.y;
#pragma unroll
    for (int r = 0; r < 4; r++) {
        int k = ty + r * 8;
        t[tx][k] = w[(size_t)(k0 + k) * N + n0 + tx];
    }
    __syncthreads();
    int idx = ty * 32 + tx;            // 0..255
#pragma unroll
    for (int r = 0; r < 2; r++) {
        int e = idx + r * 256;         // 0..511 -> (n, kpair)
        int n = e >> 4;
        int kp = (e & 15) * 2;
        o[((size_t)(n0 + n) * DM + k0 + kp) / 2] = packh2(t[n][kp], t[n][kp + 1]);
    }
}

// ============ cp.async 3-stage fp16 GEMM: 128x128x64 tile, 256 thr =========
// A tile [128 m][64 k] and B tile [128 n][64 k] halves, padded stride 72.
// MODE 0: D = (qA @ qB^T + bias) * mask, optional gate, scatter to g_K/Q/V
// MODE 1: D = (qA @ qB^T + bias) -> outp
#define LDH 72
#define GT_BYTES (128 * LDH * 2)       // 18432
#define ST_BYTES (2 * GT_BYTES)        // 36864
#define GEMM_SMEM (3 * ST_BYTES)       // 110592
#define NKT 16

template <int MODE>
__global__ void __launch_bounds__(256, 2) gemm_cp(
    const float* __restrict__ bias, const float* __restrict__ mask,
    float* __restrict__ outp, int mod, int gated, int rowoff) {
    extern __shared__ __half smh[];
    uint32_t sbase = cvta_sm(smh);

    int tid = threadIdx.x;
    int wid = tid >> 5, lane = tid & 31;
    int g = lane >> 2, u = lane & 3;
    int wm = (wid >> 2) * 64;
    int wn = (wid & 3) * 32;
    int mtile = blockIdx.y * 128;
    int ntile = blockIdx.x * 128;

    // ldmatrix lane offsets
    int mi = lane >> 3, r8 = lane & 7;
    uint32_t lmA = (uint32_t)(((mi & 1) * 8 + r8) * LDH * 2 + (mi >> 1) * 16);
    uint32_t lmB = (uint32_t)(((mi >> 1) * 8 + r8) * LDH * 2 + (mi & 1) * 16);

    // cp.async coords: 128 rows x 8 chunks(16B); idx = tid + l*256
    int rows_[4], ch_[4];
    uint32_t aoff[4], boff[4];
#pragma unroll
    for (int l = 0; l < 4; l++) {
        int idx = tid + l * 256;
        rows_[l] = idx >> 3;
        ch_[l] = (idx & 7) * 8;        // halves
        aoff[l] = (uint32_t)(rows_[l] * LDH + ch_[l]) * 2;
        boff[l] = aoff[l] + GT_BYTES;
    }

    float acc[4][4][4];
#pragma unroll
    for (int i = 0; i < 4; i++)
#pragma unroll
        for (int j = 0; j < 4; j++)
#pragma unroll
            for (int e = 0; e < 4; e++) acc[i][j][e] = 0.f;

    const __half* Aq = (const __half*)g_qA;
    const __half* Bq = (const __half*)g_qB;

#define ISSUE_TILE(KT, S) do {                                                     \
    if ((KT) < NKT) {                                                              \
        int _k0 = (KT) * 64;                                                       \
        uint32_t _sb = sbase + (uint32_t)(S) * ST_BYTES;                           \
        _Pragma("unroll")                                                          \
        for (int _l = 0; _l < 4; _l++) {                                           \
            const __half* _ga = Aq + (size_t)(mtile + rows_[_l]) * DM + _k0 + ch_[_l]; \
            asm volatile("cp.async.cg.shared.global [%0], [%1], 16;"               \
                         :: "r"(_sb + aoff[_l]), "l"(_ga) : "memory");             \
            const __half* _gb = Bq + (size_t)(ntile + rows_[_l]) * DM + _k0 + ch_[_l]; \
            asm volatile("cp.async.cg.shared.global [%0], [%1], 16;"               \
                         :: "r"(_sb + boff[_l]), "l"(_gb) : "memory");             \
        }                                                                          \
    }                                                                              \
    asm volatile("cp.async.commit_group;" ::: "memory");                           \
} while (0)

    ISSUE_TILE(0, 0);
    ISSUE_TILE(1, 1);
    asm volatile("cp.async.wait_group 1;" ::: "memory");
    __syncthreads();

    int cur = 0;
    for (int kt = 0; kt < NKT; kt++) {
        uint32_t stage = sbase + (uint32_t)cur * ST_BYTES;
        uint32_t aT = stage + (uint32_t)(wm * LDH) * 2 + lmA;
        uint32_t bT = stage + GT_BYTES + (uint32_t)(wn * LDH) * 2 + lmB;

#pragma unroll
        for (int ks = 0; ks < 4; ks++) {
            uint32_t kb = (uint32_t)(ks * 16) * 2;     // 16 halves per k-step
            uint32_t af[4][4], bf[4][2];
#pragma unroll
            for (int i = 0; i < 4; i++)
                ldsm4(af[i][0], af[i][1], af[i][2], af[i][3],
                      aT + (uint32_t)(i * 16 * LDH) * 2 + kb);
#pragma unroll
            for (int jp = 0; jp < 2; jp++)
                ldsm4(bf[2 * jp][0], bf[2 * jp][1], bf[2 * jp + 1][0], bf[2 * jp + 1][1],
                      bT + (uint32_t)(jp * 16 * LDH) * 2 + kb);
#pragma unroll
            for (int i = 0; i < 4; i++)
#pragma unroll
                for (int j = 0; j < 4; j++)
                    mma_f16(acc[i][j], af[i][0], af[i][1], af[i][2], af[i][3],
                            bf[j][0], bf[j][1]);
        }

        int nxt = cur + 2; if (nxt >= 3) nxt -= 3;
        ISSUE_TILE(kt + 2, nxt);
        asm volatile("cp.async.wait_group 1;" ::: "memory");
        __syncthreads();
        cur = cur + 1; if (cur == 3) cur = 0;
    }

    // ---- epilogue (same fragment layout as m16n8k8) ----
    int part = ntile >> 10;
#pragma unroll
    for (int i = 0; i < 4; i++) {
        int r0 = mtile + wm + i * 16 + g;
        int r1 = r0 + 8;
#pragma unroll
        for (int j = 0; j < 4; j++) {
            int col = ntile + wn + j * 8 + u * 2;
            if (MODE == 1) {
                float b0 = bias[col], b1 = bias[col + 1];
                *(float2*)(outp + (size_t)r0 * DM + col) =
                    make_float2(acc[i][j][0] + b0, acc[i][j][1] + b1);
                *(float2*)(outp + (size_t)r1 * DM + col) =
                    make_float2(acc[i][j][2] + b0, acc[i][j][3] + b1);
            } else {
                float b0 = bias[col], b1 = bias[col + 1];
                int d0 = col & 1023;
#pragma unroll
                for (int h = 0; h < 2; h++) {
                    int r = h ? r1 : r0;
                    int b = r >> 9, si = r & 511;
                    float mk = mask[r];
                    float v0 = (acc[i][j][h * 2 + 0] + b0) * mk;
                    float v1 = (acc[i][j][h * 2 + 1] + b1) * mk;
                    if (gated && part < 2) {
                        v0 *= g_gate[mod][b][d0];
                        v1 *= g_gate[mod][b][d0 + 1];
                    }
                    float* dst;
                    if (part == 0)      dst = &g_K[mod][b][rowoff + si][d0];
                    else if (part == 1) dst = &g_Q[mod][b][si][d0];
                    else                dst = &g_V[mod][b][rowoff + si][d0];
                    *(float2*)dst = make_float2(v0, v1);
                }
            }
        }
    }
}

// ================= fused flash attention (tf32 mma) =========================
#define FA_LDQ 132
#define FA_LDP 68
#define FA_SMEM (3 * 64 * FA_LDQ * 4 + 64 * FA_LDP * 4 + (64 * 6 + 128) * 4)

__global__ void __launch_bounds__(256) flash_attn(
    const float* __restrict__ mask, int mod, int Sk, int hasmem) {
    extern __shared__ char smraw[];
    uint32_t* Qs = (uint32_t*)smraw;
    uint32_t* Ks = Qs + 64 * FA_LDQ;
    uint32_t* Vs = Ks + 64 * FA_LDQ;
    uint32_t* Ps = Vs + 64 * FA_LDQ;
    float* m_s  = (float*)(Ps + 64 * FA_LDP);
    float* l_s  = m_s + 64;
    float* al_s = l_s + 64;
    float* red  = al_s + 64;     // [2][64]
    float* kms  = red + 128;

    int tid = threadIdx.x;
    int wid = tid >> 5, lane = tid & 31;
    int g = lane >> 2, u = lane & 3;
    int wm = (wid >> 1) * 16;
    int wns = (wid & 1) * 32;
    int wno = (wid & 1) * 64;
    int bh = blockIdx.y;
    int b = bh >> 3, h = bh & 7;
    int qt0 = blockIdx.x * 64;

    const float* Qg = &g_Q[mod][b][0][h * DH];
    const float* Kg = &g_K[mod][b][0][h * DH];
    const float* Vg = &g_V[mod][b][0][h * DH];

#pragma unroll
    for (int l = 0; l < 8; l++) {
        int idx = tid + l * 256;
        int row = idx >> 5;
        int c4 = (idx & 31) * 4;
        float4 v = *(const float4*)(Qg + (size_t)(qt0 + row) * DM + c4);
        uint32_t* d = &Qs[row * FA_LDQ + c4];
        d[0] = f2tf32(v.x); d[1] = f2tf32(v.y); d[2] = f2tf32(v.z); d[3] = f2tf32(v.w);
    }
    if (tid < 64) { m_s[tid] = -3.4e38f; l_s[tid] = 0.f; }

    float acc_o[8][4];
#pragma unroll
    for (int j = 0; j < 8; j++)
#pragma unroll
        for (int e = 0; e < 4; e++) acc_o[j][e] = 0.f;

    const float scl = 0.08838834764831845f;   // 1/sqrt(128)
    int r0l = wm + g, r1l = wm + g + 8;
    int nt = (Sk + 63) >> 6;

    for (int t = 0; t < nt; t++) {
        int kt0 = t * 64;
        __syncthreads();
#pragma unroll
        for (int l = 0; l < 8; l++) {
            int idx = tid + l * 256;
            int row = idx >> 5;
            int c4 = (idx & 31) * 4;
            int key = kt0 + row;
            float4 kv = make_float4(0.f, 0.f, 0.f, 0.f);
            float4 vv = make_float4(0.f, 0.f, 0.f, 0.f);
            if (key < Sk) {
                kv = *(const float4*)(Kg + (size_t)key * DM + c4);
                vv = *(const float4*)(Vg + (size_t)key * DM + c4);
            }
            uint32_t* dk = &Ks[row * FA_LDQ + c4];
            dk[0] = f2tf32(kv.x); dk[1] = f2tf32(kv.y); dk[2] = f2tf32(kv.z); dk[3] = f2tf32(kv.w);
            uint32_t* dv = &Vs[row * FA_LDQ + c4];
            dv[0] = f2tf32(vv.x); dv[1] = f2tf32(vv.y); dv[2] = f2tf32(vv.z); dv[3] = f2tf32(vv.w);
        }
        if (tid < 64) {
            int key = kt0 + tid;
            float km = 0.f;
            if (key < Sk)
                km = hasmem ? ((key == 0) ? 1.f : mask[b * SEQ + key - 1])
                            : mask[b * SEQ + key];
            kms[tid] = km;
        }
        __syncthreads();

        float s[4][4];
#pragma unroll
        for (int j = 0; j < 4; j++)
#pragma unroll
            for (int e = 0; e < 4; e++) s[j][e] = 0.f;
#pragma unroll
        for (int kk = 0; kk < 16; kk++) {
            int k8 = kk * 8;
            uint32_t a0 = Qs[r0l * FA_LDQ + k8 + u];
            uint32_t a1 = Qs[r1l * FA_LDQ + k8 + u];
            uint32_t a2 = Qs[r0l * FA_LDQ + k8 + u + 4];
            uint32_t a3 = Qs[r1l * FA_LDQ + k8 + u + 4];
#pragma unroll
            for (int j = 0; j < 4; j++) {
                int n = wns + j * 8 + g;
                uint32_t b0 = Ks[n * FA_LDQ + k8 + u];
                uint32_t b1 = Ks[n * FA_LDQ + k8 + u + 4];
                mma_tf32(s[j], a0, a1, a2, a3, b0, b1);
            }
        }
        float rm0 = -3.4e38f, rm1 = -3.4e38f;
#pragma unroll
        for (int j = 0; j < 4; j++) {
            int col = wns + j * 8 + u * 2;
            float k0m = kms[col], k1m = kms[col + 1];
            s[j][0] = (k0m != 0.f ? s[j][0] : -1e9f) * scl;
            s[j][1] = (k1m != 0.f ? s[j][1] : -1e9f) * scl;
            s[j][2] = (k0m != 0.f ? s[j][2] : -1e9f) * scl;
            s[j][3] = (k1m != 0.f ? s[j][3] : -1e9f) * scl;
            rm0 = fmaxf(rm0, fmaxf(s[j][0], s[j][1]));
            rm1 = fmaxf(rm1, fmaxf(s[j][2], s[j][3]));
        }
        rm0 = fmaxf(rm0, __shfl_xor_sync(0xffffffffu, rm0, 1));
        rm0 = fmaxf(rm0, __shfl_xor_sync(0xffffffffu, rm0, 2));
        rm1 = fmaxf(rm1, __shfl_xor_sync(0xffffffffu, rm1, 1));
        rm1 = fmaxf(rm1, __shfl_xor_sync(0xffffffffu, rm1, 2));
        if (u == 0) {
            red[(wid & 1) * 64 + r0l] = rm0;
            red[(wid & 1) * 64 + r1l] = rm1;
        }
        __syncthreads();
        if ((wid & 1) == 0 && u == 0) {
#pragma unroll
            for (int hh = 0; hh < 2; hh++) {
                int r = hh ? r1l : r0l;
                float tm = fmaxf(red[r], red[64 + r]);
                float mo = m_s[r];
                float mn = fmaxf(mo, tm);
                al_s[r] = expf(mo - mn);
                m_s[r] = mn;
            }
        }
        __syncthreads();
        float mn0 = m_s[r0l], mn1 = m_s[r1l];
        float rs0 = 0.f, rs1 = 0.f;
#pragma unroll
        for (int j = 0; j < 4; j++) {
            int col = wns + j * 8 + u * 2;
            float p0 = expf(s[j][0] - mn0);
            float p1 = expf(s[j][1] - mn0);
            float p2 = expf(s[j][2] - mn1);
            float p3 = expf(s[j][3] - mn1);
            rs0 += p0 + p1; rs1 += p2 + p3;
            Ps[r0l * FA_LDP + col]     = f2tf32(p0);
            Ps[r0l * FA_LDP + col + 1] = f2tf32(p1);
            Ps[r1l * FA_LDP + col]     = f2tf32(p2);
            Ps[r1l * FA_LDP + col + 1] = f2tf32(p3);
        }
        rs0 += __shfl_xor_sync(0xffffffffu, rs0, 1);
        rs0 += __shfl_xor_sync(0xffffffffu, rs0, 2);
        rs1 += __shfl_xor_sync(0xffffffffu, rs1, 1);
        rs1 += __shfl_xor_sync(0xffffffffu, rs1, 2);
        if (u == 0) {
            red[(wid & 1) * 64 + r0l] = rs0;
            red[(wid & 1) * 64 + r1l] = rs1;
        }
        __syncthreads();
        if ((wid & 1) == 0 && u == 0) {
            l_s[r0l] = l_s[r0l] * al_s[r0l] + red[r0l] + red[64 + r0l];
            l_s[r1l] = l_s[r1l] * al_s[r1l] + red[r1l] + red[64 + r1l];
        }
        float a0s = al_s[r0l], a1s = al_s[r1l];
#pragma unroll
        for (int j = 0; j < 8; j++) {
            acc_o[j][0] *= a0s; acc_o[j][1] *= a0s;
            acc_o[j][2] *= a1s; acc_o[j][3] *= a1s;
        }
#pragma unroll
        for (int ks = 0; ks < 8; ks++) {
            int k8 = ks * 8;
            uint32_t a0 = Ps[r0l * FA_LDP + k8 + u];
            uint32_t a1 = Ps[r1l * FA_LDP + k8 + u];
            uint32_t a2 = Ps[r0l * FA_LDP + k8 + u + 4];
            uint32_t a3 = Ps[r1l * FA_LDP + k8 + u + 4];
#pragma unroll
            for (int j = 0; j < 8; j++) {
                int n = wno + j * 8 + g;
                uint32_t b0 = Vs[(k8 + u) * FA_LDQ + n];
                uint32_t b1 = Vs[(k8 + u + 4) * FA_LDQ + n];
                mma_tf32(acc_o[j], a0, a1, a2, a3, b0, b1);
            }
        }
    }
    __syncthreads();
    float inv0 = 1.f / l_s[r0l];
    float inv1 = 1.f / l_s[r1l];
    int qr0 = qt0 + r0l, qr1 = qt0 + r1l;
#pragma unroll
    for (int j = 0; j < 8; j++) {
        int col = h * DH + wno + j * 8 + u * 2;
        *(float2*)&g_U[b][qr0][col] =
            make_float2(acc_o[j][0] * inv0, acc_o[j][1] * inv0);
        *(float2*)&g_U[b][qr1][col] =
            make_float2(acc_o[j][2] * inv1, acc_o[j][3] * inv1);
    }
}

// ---------------- masked mean (parallel over d-chunks) ----------------
__global__ void mean_kernel(const float* __restrict__ x, const float* __restrict__ mask, int slot) {
    int b = blockIdx.y;
    int d = blockIdx.x * 128 + threadIdx.x;
    __shared__ float sm[SEQ];
    __shared__ float smsum;
    for (int i = threadIdx.x; i < SEQ; i += 128) sm[i] = mask[b * SEQ + i];
    __syncthreads();
    if (threadIdx.x == 0) {
        float s = 0.f;
        for (int i = 0; i < SEQ; i++) s += sm[i];
        smsum = s;
    }
    __syncthreads();
    float inv = 1.f / smsum;
    float acc = 0.f;
    for (int i = 0; i < SEQ; i++) acc += x[(size_t)(b * SEQ + i) * DM + d] * sm[i];
    g_mean[slot][b][d] = acc * inv;
}

// ---------------- gate = 1 + sigmoid(relu(mean) @ w + b), 4-way k-split -----
__global__ void __launch_bounds__(512) gate_kernel(
    int mean_slot, const float* __restrict__ w,
    const float* __restrict__ bias, int gate_slot) {
    int b = blockIdx.y;
    int tx = threadIdx.x;
    int dl = tx & 127, kg = tx >> 7;          // 128 d-lanes x 4 k-groups
    int d = blockIdx.x * 128 + dl;
    __shared__ float sm[DM];
    __shared__ float part[4][128];
    for (int k = tx; k < DM; k += 512) sm[k] = fmaxf(g_mean[mean_slot][b][k], 0.f);
    __syncthreads();
    float acc = 0.f;
    int k0 = kg * 256;
    for (int k = k0; k < k0 + 256; k++) acc = fmaf(sm[k], w[(size_t)k * DM + d], acc);
    part[kg][dl] = acc;
    __syncthreads();
    if (kg == 0) {
        float s = part[0][dl] + part[1][dl] + part[2][dl] + part[3][dl] + bias[d];
        g_gate[gate_slot][b][d] = 1.f + 1.f / (1.f + expf(-s));
    }
}

// ---------------- memory tokens ----------------
__global__ void memtok_kernel(const float* __restrict__ mvk, const float* __restrict__ mvv,
                              const float* __restrict__ mck, const float* __restrict__ mcv) {
    int b = blockIdx.y;
    int d = blockIdx.x * 128 + threadIdx.x;
    float gv = g_gate[0][b][d];
    g_K[0][b][0][d] = 32.f * mvk[d] * gv;
    g_V[0][b][0][d] = mvv[d];
    g_K[2][b][0][d] = 32.f * mck[d];
    g_V[2][b][0][d] = mcv[d];
}

// ---------------- orchestration ----------------
extern "C" void kernel_launch(void* const* d_in, const int* in_sizes, int n_in,
                              void* d_out, int out_size) {
    const float* v      = (const float*)d_in[0];
    const float* q      = (const float*)d_in[1];
    const float* c      = (const float*)d_in[2];
    const float* v_mask = (const float*)d_in[3];
    const float* q_mask = (const float*)d_in[4];
    const float* c_mask = (const float*)d_in[5];
    const float* v4q_w  = (const float*)d_in[6];
    const float* v4q_b  = (const float*)d_in[7];
    const float* q4v_w  = (const float*)d_in[8];
    const float* q4v_b  = (const float*)d_in[9];
    const float* v_lin_w = (const float*)d_in[10];
    const float* v_lin_b = (const float*)d_in[11];
    const float* q_lin_w = (const float*)d_in[12];
    const float* q_lin_b = (const float*)d_in[13];
    const float* c_lin_w = (const float*)d_in[14];
    const float* c_lin_b = (const float*)d_in[15];
    const float* m_v_k  = (const float*)d_in[16];
    const float* m_v_v  = (const float*)d_in[17];
    const float* m_c_k  = (const float*)d_in[18];
    const float* m_c_v  = (const float*)d_in[19];
    const float* v_out_w = (const float*)d_in[20];
    const float* v_out_b = (const float*)d_in[21];
    const float* q_out_w = (const float*)d_in[22];
    const float* q_out_b = (const float*)d_in[23];
    const float* c_out_w = (const float*)d_in[24];
    const float* c_out_b = (const float*)d_in[25];
    float* out = (float*)d_out;

    static int attr_set = 0;
    if (!attr_set) {
        cudaFuncSetAttribute(flash_attn, cudaFuncAttributeMaxDynamicSharedMemorySize, FA_SMEM);
        cudaFuncSetAttribute(gemm_cp<0>, cudaFuncAttributeMaxDynamicSharedMemorySize, GEMM_SMEM);
        cudaFuncSetAttribute(gemm_cp<1>, cudaFuncAttributeMaxDynamicSharedMemorySize, GEMM_SMEM);
        attr_set = 1;
    }

    const int NA = BZ * SEQ * DM;       // 8388608

    // 1) masked means
    mean_kernel<<<dim3(8, BZ), 128>>>(v, v_mask, 0);
    mean_kernel<<<dim3(8, BZ), 128>>>(q, q_mask, 1);

    // 2) gates
    gate_kernel<<<dim3(8, BZ), 512>>>(1, q4v_w, q4v_b, 0);
    gate_kernel<<<dim3(8, BZ), 512>>>(0, v4q_w, v4q_b, 1);

    // 3) memory tokens
    memtok_kernel<<<dim3(8, BZ), 128>>>(m_v_k, m_v_v, m_c_k, m_c_v);

    // 4) trans GEMMs: quantize (A straight, W transposed) then cp.async GEMM
    const float* xin[3]  = {v, q, c};
    const float* lw[3]   = {v_lin_w, q_lin_w, c_lin_w};
    const float* lb[3]   = {v_lin_b, q_lin_b, c_lin_b};
    const float* masks[3] = {v_mask, q_mask, c_mask};
    const int    gatedv[3] = {1, 1, 0};
    const int    rowoffv[3] = {1, 0, 1};

    uint32_t* qA = nullptr; cudaGetSymbolAddress((void**)&qA, g_qA);
    uint32_t* qB = nullptr; cudaGetSymbolAddress((void**)&qB, g_qB);

    dim3 tg(N3 / 128, (BZ * SEQ) / 128);
    for (int m = 0; m < 3; m++) {
        quant_kernel<<<NA / 1024, 256>>>(xin[m], qA, NA, 0);
        quantT_kernel<<<dim3(N3 / 32, DM / 32), dim3(32, 8)>>>(lw[m], qB, N3);
        gemm_cp<0><<<tg, 256, GEMM_SMEM>>>(lb[m], masks[m], nullptr, m,
                                           gatedv[m], rowoffv[m]);
    }

    // 5) per-modality fused flash attention + out projection
    const float* ows[3] = {v_out_w, q_out_w, c_out_w};
    const float* obs[3] = {v_out_b, q_out_b, c_out_b};
    const int    sks[3] = {SKM, SEQ, SKM};
    const int    hasm[3] = {1, 0, 1};

    dim3 og(DM / 128, (BZ * SEQ) / 128);
    for (int m = 0; m < 3; m++) {
        flash_attn<<<dim3(SEQ / 64, BZ * NH), 256, FA_SMEM>>>(masks[m], m, sks[m], hasm[m]);
        quant_kernel<<<NA / 1024, 256>>>(xin[m], qA, NA, 1);       // x + U
        quantT_kernel<<<dim3(DM / 32, DM / 32), dim3(32, 8)>>>(ows[m], qB, DM);
        gemm_cp<1><<<og, 256, GEMM_SMEM>>>(obs[m], nullptr,
                                           out + (size_t)m * BZ * SEQ * DM,
                                           0, 0, 0);
    }
}

// round 15
// speedup vs baseline: 2.2730x; 1.5579x over previous
#include <cuda_runtime.h>
#include <cuda_fp16.h>
#include <math.h>
#include <stdint.h>

#define BZ   16
#define SEQ  512
#define DM   1024
#define NH   8
#define DH   128
#define SKM  513          // keys with memory token
#define N3   3072

// ---------------- static scratch (device globals; allocation-free) ----------
__device__ float g_mean[2][BZ][DM];
__device__ float g_gate[2][BZ][DM];
__device__ __half g_Kh[3][BZ][SEQ + 1][DM];
__device__ __half g_Qh[3][BZ][SEQ][DM];
__device__ __half g_Vh[3][BZ][SEQ + 1][DM];
__device__ float g_U[BZ][SEQ][DM];
__device__ uint32_t g_qA[BZ * SEQ * DM / 2];   // fp16 pairs of A operand [M][1024]
__device__ uint32_t g_qB[N3 * DM / 2];         // fp16 pairs of W^T operand [N][1024]

__device__ __forceinline__ void mma_f16(float* c, uint32_t a0, uint32_t a1,
                                        uint32_t a2, uint32_t a3,
                                        uint32_t b0, uint32_t b1) {
    asm volatile(
        "mma.sync.aligned.m16n8k16.row.col.f32.f16.f16.f32 "
        "{%0,%1,%2,%3}, {%4,%5,%6,%7}, {%8,%9}, {%0,%1,%2,%3};"
        : "+f"(c[0]), "+f"(c[1]), "+f"(c[2]), "+f"(c[3])
        : "r"(a0), "r"(a1), "r"(a2), "r"(a3), "r"(b0), "r"(b1));
}
__device__ __forceinline__ void ldsm4(uint32_t& r0, uint32_t& r1, uint32_t& r2,
                                      uint32_t& r3, uint32_t addr) {
    asm volatile("ldmatrix.sync.aligned.m8n8.x4.shared.b16 {%0,%1,%2,%3}, [%4];"
                 : "=r"(r0), "=r"(r1), "=r"(r2), "=r"(r3) : "r"(addr));
}
__device__ __forceinline__ void ldsm4t(uint32_t& r0, uint32_t& r1, uint32_t& r2,
                                       uint32_t& r3, uint32_t addr) {
    asm volatile("ldmatrix.sync.aligned.m8n8.x4.trans.shared.b16 {%0,%1,%2,%3}, [%4];"
                 : "=r"(r0), "=r"(r1), "=r"(r2), "=r"(r3) : "r"(addr));
}
__device__ __forceinline__ uint32_t cvta_sm(const void* p) {
    uint32_t a;
    asm("{ .reg .u64 t; cvta.to.shared.u64 t, %1; cvt.u32.u64 %0, t; }" : "=r"(a) : "l"(p));
    return a;
}
__device__ __forceinline__ uint32_t packh2(float a, float b) {
    __half2 h = __floats2half2_rn(a, b);
    return *(uint32_t*)&h;
}

// ---------------- fp16 quantization pre-pass (A path) ----------------
// MODE 0: o = h(relu(x));  1: o = h(x + g_U)
__global__ void quant_kernel(const float* __restrict__ x, uint32_t* __restrict__ o,
                             int n, int mode) {
    int i = (blockIdx.x * 256 + threadIdx.x) * 4;
    if (i >= n) return;
    float4 v = *(const float4*)(x + i);
    if (mode == 0) {
        v.x = fmaxf(v.x, 0.f); v.y = fmaxf(v.y, 0.f);
        v.z = fmaxf(v.z, 0.f); v.w = fmaxf(v.w, 0.f);
    } else {
        float4 u = *(const float4*)(&g_U[0][0][0] + i);
        v.x += u.x; v.y += u.y; v.z += u.z; v.w += u.w;
    }
    *(uint2*)(o + i / 2) = make_uint2(packh2(v.x, v.y), packh2(v.z, v.w));
}

// ------- transposed quant for W: [1024][N] fp32 -> fp16 pairs [N][1024] -----
__global__ void quantT_kernel(const float* __restrict__ w, uint32_t* __restrict__ o, int N) {
    __shared__ float t[32][33];
    int n0 = blockIdx.x * 32, k0 = blockIdx.y * 32;
    int tx = threadIdx.x, ty = threadIdx.y;
#pragma unroll
    for (int r = 0; r < 4; r++) {
        int k = ty + r * 8;
        t[tx][k] = w[(size_t)(k0 + k) * N + n0 + tx];
    }
    __syncthreads();
    int idx = ty * 32 + tx;            // 0..255
#pragma unroll
    for (int r = 0; r < 2; r++) {
        int e = idx + r * 256;         // 0..511 -> (n, kpair)
        int n = e >> 4;
        int kp = (e & 15) * 2;
        o[((size_t)(n0 + n) * DM + k0 + kp) / 2] = packh2(t[n][kp], t[n][kp + 1]);
    }
}

// ============ cp.async 3-stage fp16 GEMM: 128x128x64 tile, 256 thr =========
#define LDH 72
#define GT_BYTES (128 * LDH * 2)       // 18432
#define ST_BYTES (2 * GT_BYTES)        // 36864
#define GEMM_SMEM (3 * ST_BYTES)       // 110592
#define NKT 16

template <int MODE>
__global__ void __launch_bounds__(256, 2) gemm_cp(
    const float* __restrict__ bias, const float* __restrict__ mask,
    float* __restrict__ outp, int mod, int gated, int rowoff) {
    extern __shared__ __half smh[];
    uint32_t sbase = cvta_sm(smh);

    int tid = threadIdx.x;
    int wid = tid >> 5, lane = tid & 31;
    int g = lane >> 2, u = lane & 3;
    int wm = (wid >> 2) * 64;
    int wn = (wid & 3) * 32;
    int mtile = blockIdx.y * 128;
    int ntile = blockIdx.x * 128;

    int mi = lane >> 3, r8 = lane & 7;
    uint32_t lmA = (uint32_t)(((mi & 1) * 8 + r8) * LDH * 2 + (mi >> 1) * 16);
    uint32_t lmB = (uint32_t)(((mi >> 1) * 8 + r8) * LDH * 2 + (mi & 1) * 16);

    int rows_[4], ch_[4];
    uint32_t aoff[4], boff[4];
#pragma unroll
    for (int l = 0; l < 4; l++) {
        int idx = tid + l * 256;
        rows_[l] = idx >> 3;
        ch_[l] = (idx & 7) * 8;        // halves
        aoff[l] = (uint32_t)(rows_[l] * LDH + ch_[l]) * 2;
        boff[l] = aoff[l] + GT_BYTES;
    }

    float acc[4][4][4];
#pragma unroll
    for (int i = 0; i < 4; i++)
#pragma unroll
        for (int j = 0; j < 4; j++)
#pragma unroll
            for (int e = 0; e < 4; e++) acc[i][j][e] = 0.f;

    const __half* Aq = (const __half*)g_qA;
    const __half* Bq = (const __half*)g_qB;

#define ISSUE_TILE(KT, S) do {                                                     \
    if ((KT) < NKT) {                                                              \
        int _k0 = (KT) * 64;                                                       \
        uint32_t _sb = sbase + (uint32_t)(S) * ST_BYTES;                           \
        _Pragma("unroll")                                                          \
        for (int _l = 0; _l < 4; _l++) {                                           \
            const __half* _ga = Aq + (size_t)(mtile + rows_[_l]) * DM + _k0 + ch_[_l]; \
            asm volatile("cp.async.cg.shared.global [%0], [%1], 16;"               \
                         :: "r"(_sb + aoff[_l]), "l"(_ga) : "memory");             \
            const __half* _gb = Bq + (size_t)(ntile + rows_[_l]) * DM + _k0 + ch_[_l]; \
            asm volatile("cp.async.cg.shared.global [%0], [%1], 16;"               \
                         :: "r"(_sb + boff[_l]), "l"(_gb) : "memory");             \
        }                                                                          \
    }                                                                              \
    asm volatile("cp.async.commit_group;" ::: "memory");                           \
} while (0)

    ISSUE_TILE(0, 0);
    ISSUE_TILE(1, 1);
    asm volatile("cp.async.wait_group 1;" ::: "memory");
    __syncthreads();

    int cur = 0;
    for (int kt = 0; kt < NKT; kt++) {
        uint32_t stage = sbase + (uint32_t)cur * ST_BYTES;
        uint32_t aT = stage + (uint32_t)(wm * LDH) * 2 + lmA;
        uint32_t bT = stage + GT_BYTES + (uint32_t)(wn * LDH) * 2 + lmB;

#pragma unroll
        for (int ks = 0; ks < 4; ks++) {
            uint32_t kb = (uint32_t)(ks * 16) * 2;
            uint32_t af[4][4], bf[4][2];
#pragma unroll
            for (int i = 0; i < 4; i++)
                ldsm4(af[i][0], af[i][1], af[i][2], af[i][3],
                      aT + (uint32_t)(i * 16 * LDH) * 2 + kb);
#pragma unroll
            for (int jp = 0; jp < 2; jp++)
                ldsm4(bf[2 * jp][0], bf[2 * jp][1], bf[2 * jp + 1][0], bf[2 * jp + 1][1],
                      bT + (uint32_t)(jp * 16 * LDH) * 2 + kb);
#pragma unroll
            for (int i = 0; i < 4; i++)
#pragma unroll
                for (int j = 0; j < 4; j++)
                    mma_f16(acc[i][j], af[i][0], af[i][1], af[i][2], af[i][3],
                            bf[j][0], bf[j][1]);
        }

        int nxt = cur + 2; if (nxt >= 3) nxt -= 3;
        ISSUE_TILE(kt + 2, nxt);
        asm volatile("cp.async.wait_group 1;" ::: "memory");
        __syncthreads();
        cur = cur + 1; if (cur == 3) cur = 0;
    }

    // ---- epilogue ----
    int part = ntile >> 10;
#pragma unroll
    for (int i = 0; i < 4; i++) {
        int r0 = mtile + wm + i * 16 + g;
        int r1 = r0 + 8;
#pragma unroll
        for (int j = 0; j < 4; j++) {
            int col = ntile + wn + j * 8 + u * 2;
            if (MODE == 1) {
                float b0 = bias[col], b1 = bias[col + 1];
                *(float2*)(outp + (size_t)r0 * DM + col) =
                    make_float2(acc[i][j][0] + b0, acc[i][j][1] + b1);
                *(float2*)(outp + (size_t)r1 * DM + col) =
                    make_float2(acc[i][j][2] + b0, acc[i][j][3] + b1);
            } else {
                float b0 = bias[col], b1 = bias[col + 1];
                int d0 = col & 1023;
#pragma unroll
                for (int h = 0; h < 2; h++) {
                    int r = h ? r1 : r0;
                    int b = r >> 9, si = r & 511;
                    float mk = mask[r];
                    float v0 = (acc[i][j][h * 2 + 0] + b0) * mk;
                    float v1 = (acc[i][j][h * 2 + 1] + b1) * mk;
                    if (gated && part < 2) {
                        v0 *= g_gate[mod][b][d0];
                        v1 *= g_gate[mod][b][d0 + 1];
                    }
                    __half* dst;
                    if (part == 0)      dst = &g_Kh[mod][b][rowoff + si][d0];
                    else if (part == 1) dst = &g_Qh[mod][b][si][d0];
                    else                dst = &g_Vh[mod][b][rowoff + si][d0];
                    *(uint32_t*)dst = packh2(v0, v1);
                }
            }
        }
    }
}

// ================= fused flash attention (fp16 mma) =========================
// block = 64 q-rows x (b,h). 8 warps: 4(m,16 rows) x 2(n: 32 keys / 64 dh).
#define FA_LD  136
#define FA_LDP 72
#define FA_SMEM ((3 * 64 * FA_LD + 64 * FA_LDP) * 2 + (64 * 3 + 128 + 64) * 4)

__global__ void __launch_bounds__(256) flash_attn(
    const float* __restrict__ mask, int mod, int Sk, int hasmem) {
    extern __shared__ char smraw[];
    __half* Qh = (__half*)smraw;
    __half* Kh = Qh + 64 * FA_LD;
    __half* Vh = Kh + 64 * FA_LD;
    __half* Ph = Vh + 64 * FA_LD;
    float* m_s  = (float*)(Ph + 64 * FA_LDP);
    float* l_s  = m_s + 64;
    float* al_s = l_s + 64;
    float* red  = al_s + 64;     // [2][64]
    float* kms  = red + 128;

    int tid = threadIdx.x;
    int wid = tid >> 5, lane = tid & 31;
    int g = lane >> 2, u = lane & 3;
    int mi = lane >> 3, r8 = lane & 7;
    int wm = (wid >> 1) * 16;
    int wns = (wid & 1) * 32;
    int wno = (wid & 1) * 64;
    int bh = blockIdx.y;
    int b = bh >> 3, h = bh & 7;
    int qt0 = blockIdx.x * 64;

    const __half* Qg = &g_Qh[mod][b][0][h * DH];
    const __half* Kg = &g_Kh[mod][b][0][h * DH];
    const __half* Vg = &g_Vh[mod][b][0][h * DH];

    uint32_t smQ = cvta_sm(Qh), smK = cvta_sm(Kh);
    uint32_t smV = cvta_sm(Vh), smP = cvta_sm(Ph);
    uint32_t lmA  = (uint32_t)(((mi & 1) * 8 + r8) * FA_LD * 2 + (mi >> 1) * 16);
    uint32_t lmB  = (uint32_t)(((mi >> 1) * 8 + r8) * FA_LD * 2 + (mi & 1) * 16);
    uint32_t lmAP = (uint32_t)(((mi & 1) * 8 + r8) * FA_LDP * 2 + (mi >> 1) * 16);
    uint32_t lmVT = (uint32_t)((lane & 15) * FA_LD * 2 + (lane >> 4) * 16);

    // load Q tile once (fp16 copy)
#pragma unroll
    for (int l = 0; l < 4; l++) {
        int idx = tid + l * 256;
        int row = idx >> 4;
        int c8 = (idx & 15) * 8;
        *(uint4*)&Qh[row * FA_LD + c8] =
            *(const uint4*)(Qg + (size_t)(qt0 + row) * DM + c8);
    }
    if (tid < 64) { m_s[tid] = -3.4e38f; l_s[tid] = 0.f; }

    float acc_o[8][4];
#pragma unroll
    for (int j = 0; j < 8; j++)
#pragma unroll
        for (int e = 0; e < 4; e++) acc_o[j][e] = 0.f;

    const float scl = 0.08838834764831845f;   // 1/sqrt(128)
    int r0l = wm + g, r1l = wm + g + 8;
    int nt = (Sk + 63) >> 6;

    for (int t = 0; t < nt; t++) {
        int kt0 = t * 64;
        __syncthreads();   // A: protect Kh/Vh/Ph vs prev iter reads
#pragma unroll
        for (int l = 0; l < 4; l++) {
            int idx = tid + l * 256;
            int row = idx >> 4;
            int c8 = (idx & 15) * 8;
            int key = kt0 + row;
            uint4 kv = make_uint4(0, 0, 0, 0), vv = make_uint4(0, 0, 0, 0);
            if (key < Sk) {
                kv = *(const uint4*)(Kg + (size_t)key * DM + c8);
                vv = *(const uint4*)(Vg + (size_t)key * DM + c8);
            }
            *(uint4*)&Kh[row * FA_LD + c8] = kv;
            *(uint4*)&Vh[row * FA_LD + c8] = vv;
        }
        if (tid < 64) {
            int key = kt0 + tid;
            float km = 0.f;
            if (key < Sk)
                km = hasmem ? ((key == 0) ? 1.f : mask[b * SEQ + key - 1])
                            : mask[b * SEQ + key];
            kms[tid] = km;
        }
        __syncthreads();   // B

        // ---- S = Q @ K^T (16x32 per warp, k=128, fp16) ----
        float s[4][4];
#pragma unroll
        for (int j = 0; j < 4; j++)
#pragma unroll
            for (int e = 0; e < 4; e++) s[j][e] = 0.f;
        uint32_t aQ = smQ + (uint32_t)(wm * FA_LD) * 2 + lmA;
        uint32_t bK = smK + (uint32_t)(wns * FA_LD) * 2 + lmB;
#pragma unroll
        for (int ks = 0; ks < 8; ks++) {
            uint32_t kb = (uint32_t)(ks * 16) * 2;
            uint32_t a0, a1, a2, a3;
            uint32_t bf[4][2];
            ldsm4(a0, a1, a2, a3, aQ + kb);
#pragma unroll
            for (int jp = 0; jp < 2; jp++)
                ldsm4(bf[2 * jp][0], bf[2 * jp][1], bf[2 * jp + 1][0], bf[2 * jp + 1][1],
                      bK + (uint32_t)(jp * 16 * FA_LD) * 2 + kb);
#pragma unroll
            for (int j = 0; j < 4; j++)
                mma_f16(s[j], a0, a1, a2, a3, bf[j][0], bf[j][1]);
        }

        // ---- mask + scale + row max ----
        float rm0 = -3.4e38f, rm1 = -3.4e38f;
#pragma unroll
        for (int j = 0; j < 4; j++) {
            int col = wns + j * 8 + u * 2;
            float k0m = kms[col], k1m = kms[col + 1];
            s[j][0] = (k0m != 0.f ? s[j][0] : -1e9f) * scl;
            s[j][1] = (k1m != 0.f ? s[j][1] : -1e9f) * scl;
            s[j][2] = (k0m != 0.f ? s[j][2] : -1e9f) * scl;
            s[j][3] = (k1m != 0.f ? s[j][3] : -1e9f) * scl;
            rm0 = fmaxf(rm0, fmaxf(s[j][0], s[j][1]));
            rm1 = fmaxf(rm1, fmaxf(s[j][2], s[j][3]));
        }
        rm0 = fmaxf(rm0, __shfl_xor_sync(0xffffffffu, rm0, 1));
        rm0 = fmaxf(rm0, __shfl_xor_sync(0xffffffffu, rm0, 2));
        rm1 = fmaxf(rm1, __shfl_xor_sync(0xffffffffu, rm1, 1));
        rm1 = fmaxf(rm1, __shfl_xor_sync(0xffffffffu, rm1, 2));
        if (u == 0) {
            red[(wid & 1) * 64 + r0l] = rm0;
            red[(wid & 1) * 64 + r1l] = rm1;
        }
        __syncthreads();   // C
        if ((wid & 1) == 0 && u == 0) {
#pragma unroll
            for (int hh = 0; hh < 2; hh++) {
                int r = hh ? r1l : r0l;
                float tm = fmaxf(red[r], red[64 + r]);
                float mo = m_s[r];
                float mn = fmaxf(mo, tm);
                al_s[r] = expf(mo - mn);
                m_s[r] = mn;
            }
        }
        __syncthreads();   // D
        float mn0 = m_s[r0l], mn1 = m_s[r1l];
        float rs0 = 0.f, rs1 = 0.f;
        uint32_t* Ph32 = (uint32_t*)Ph;
#pragma unroll
        for (int j = 0; j < 4; j++) {
            int col = wns + j * 8 + u * 2;
            float p0 = expf(s[j][0] - mn0);
            float p1 = expf(s[j][1] - mn0);
            float p2 = expf(s[j][2] - mn1);
            float p3 = expf(s[j][3] - mn1);
            rs0 += p0 + p1; rs1 += p2 + p3;
            Ph32[(r0l * FA_LDP + col) >> 1] = packh2(p0, p1);
            Ph32[(r1l * FA_LDP + col) >> 1] = packh2(p2, p3);
        }
        rs0 += __shfl_xor_sync(0xffffffffu, rs0, 1);
        rs0 += __shfl_xor_sync(0xffffffffu, rs0, 2);
        rs1 += __shfl_xor_sync(0xffffffffu, rs1, 1);
        rs1 += __shfl_xor_sync(0xffffffffu, rs1, 2);
        if (u == 0) {
            red[(wid & 1) * 64 + r0l] = rs0;
            red[(wid & 1) * 64 + r1l] = rs1;
        }
        __syncthreads();   // E: Ph + sums visible
        if ((wid & 1) == 0 && u == 0) {
            l_s[r0l] = l_s[r0l] * al_s[r0l] + red[r0l] + red[64 + r0l];
            l_s[r1l] = l_s[r1l] * al_s[r1l] + red[r1l] + red[64 + r1l];
        }
        // rescale O, then O += P @ V (fp16; V row-major via ldmatrix.trans)
        float a0s = al_s[r0l], a1s = al_s[r1l];
#pragma unroll
        for (int j = 0; j < 8; j++) {
            acc_o[j][0] *= a0s; acc_o[j][1] *= a0s;
            acc_o[j][2] *= a1s; acc_o[j][3] *= a1s;
        }
        uint32_t aP = smP + (uint32_t)(wm * FA_LDP) * 2 + lmAP;
#pragma unroll
        for (int ks = 0; ks < 4; ks++) {
            uint32_t kb = (uint32_t)(ks * 16) * 2;
            uint32_t a0, a1, a2, a3;
            uint32_t bf[8][2];
            ldsm4(a0, a1, a2, a3, aP + kb);
            uint32_t vbase = smV + (uint32_t)(ks * 16 * FA_LD) * 2 +
                             (uint32_t)(wno * 2) + lmVT;
#pragma unroll
            for (int jp = 0; jp < 4; jp++)
                ldsm4t(bf[2 * jp][0], bf[2 * jp][1], bf[2 * jp + 1][0], bf[2 * jp + 1][1],
                       vbase + (uint32_t)(jp * 16) * 2);
#pragma unroll
            for (int j = 0; j < 8; j++)
                mma_f16(acc_o[j], a0, a1, a2, a3, bf[j][0], bf[j][1]);
        }
    }
    __syncthreads();
    float inv0 = 1.f / l_s[r0l];
    float inv1 = 1.f / l_s[r1l];
    int qr0 = qt0 + r0l, qr1 = qt0 + r1l;
#pragma unroll
    for (int j = 0; j < 8; j++) {
        int col = h * DH + wno + j * 8 + u * 2;
        *(float2*)&g_U[b][qr0][col] =
            make_float2(acc_o[j][0] * inv0, acc_o[j][1] * inv0);
        *(float2*)&g_U[b][qr1][col] =
            make_float2(acc_o[j][2] * inv1, acc_o[j][3] * inv1);
    }
}

// ---------------- masked mean (parallel over d-chunks) ----------------
__global__ void mean_kernel(const float* __restrict__ x, const float* __restrict__ mask, int slot) {
    int b = blockIdx.y;
    int d = blockIdx.x * 128 + threadIdx.x;
    __shared__ float sm[SEQ];
    __shared__ float smsum;
    for (int i = threadIdx.x; i < SEQ; i += 128) sm[i] = mask[b * SEQ + i];
    __syncthreads();
    if (threadIdx.x == 0) {
        float s = 0.f;
        for (int i = 0; i < SEQ; i++) s += sm[i];
        smsum = s;
    }
    __syncthreads();
    float inv = 1.f / smsum;
    float acc = 0.f;
    for (int i = 0; i < SEQ; i++) acc += x[(size_t)(b * SEQ + i) * DM + d] * sm[i];
    g_mean[slot][b][d] = acc * inv;
}

// ---------------- gate = 1 + sigmoid(relu(mean) @ w + b), 4-way k-split -----
__global__ void __launch_bounds__(512) gate_kernel(
    int mean_slot, const float* __restrict__ w,
    const float* __restrict__ bias, int gate_slot) {
    int b = blockIdx.y;
    int tx = threadIdx.x;
    int dl = tx & 127, kg = tx >> 7;
    int d = blockIdx.x * 128 + dl;
    __shared__ float sm[DM];
    __shared__ float part[4][128];
    for (int k = tx; k < DM; k += 512) sm[k] = fmaxf(g_mean[mean_slot][b][k], 0.f);
    __syncthreads();
    float acc = 0.f;
    int k0 = kg * 256;
    for (int k = k0; k < k0 + 256; k++) acc = fmaf(sm[k], w[(size_t)k * DM + d], acc);
    part[kg][dl] = acc;
    __syncthreads();
    if (kg == 0) {
        float s = part[0][dl] + part[1][dl] + part[2][dl] + part[3][dl] + bias[d];
        g_gate[gate_slot][b][d] = 1.f + 1.f / (1.f + expf(-s));
    }
}

// ---------------- memory tokens (fp16 K/V row 0) ----------------
__global__ void memtok_kernel(const float* __restrict__ mvk, const float* __restrict__ mvv,
                              const float* __restrict__ mck, const float* __restrict__ mcv) {
    int b = blockIdx.y;
    int d = blockIdx.x * 128 + threadIdx.x;
    float gv = g_gate[0][b][d];
    g_Kh[0][b][0][d] = __float2half(32.f * mvk[d] * gv);
    g_Vh[0][b][0][d] = __float2half(mvv[d]);
    g_Kh[2][b][0][d] = __float2half(32.f * mck[d]);
    g_Vh[2][b][0][d] = __float2half(mcv[d]);
}

// ---------------- orchestration ----------------
extern "C" void kernel_launch(void* const* d_in, const int* in_sizes, int n_in,
                              void* d_out, int out_size) {
    const float* v      = (const float*)d_in[0];
    const float* q      = (const float*)d_in[1];
    const float* c      = (const float*)d_in[2];
    const float* v_mask = (const float*)d_in[3];
    const float* q_mask = (const float*)d_in[4];
    const float* c_mask = (const float*)d_in[5];
    const float* v4q_w  = (const float*)d_in[6];
    const float* v4q_b  = (const float*)d_in[7];
    const float* q4v_w  = (const float*)d_in[8];
    const float* q4v_b  = (const float*)d_in[9];
    const float* v_lin_w = (const float*)d_in[10];
    const float* v_lin_b = (const float*)d_in[11];
    const float* q_lin_w = (const float*)d_in[12];
    const float* q_lin_b = (const float*)d_in[13];
    const float* c_lin_w = (const float*)d_in[14];
    const float* c_lin_b = (const float*)d_in[15];
    const float* m_v_k  = (const float*)d_in[16];
    const float* m_v_v  = (const float*)d_in[17];
    const float* m_c_k  = (const float*)d_in[18];
    const float* m_c_v  = (const float*)d_in[19];
    const float* v_out_w = (const float*)d_in[20];
    const float* v_out_b = (const float*)d_in[21];
    const float* q_out_w = (const float*)d_in[22];
    const float* q_out_b = (const float*)d_in[23];
    const float* c_out_w = (const float*)d_in[24];
    const float* c_out_b = (const float*)d_in[25];
    float* out = (float*)d_out;

    static int attr_set = 0;
    if (!attr_set) {
        cudaFuncSetAttribute(flash_attn, cudaFuncAttributeMaxDynamicSharedMemorySize, FA_SMEM);
        cudaFuncSetAttribute(gemm_cp<0>, cudaFuncAttributeMaxDynamicSharedMemorySize, GEMM_SMEM);
        cudaFuncSetAttribute(gemm_cp<1>, cudaFuncAttributeMaxDynamicSharedMemorySize, GEMM_SMEM);
        attr_set = 1;
    }

    const int NA = BZ * SEQ * DM;       // 8388608

    // 1) masked means
    mean_kernel<<<dim3(8, BZ), 128>>>(v, v_mask, 0);
    mean_kernel<<<dim3(8, BZ), 128>>>(q, q_mask, 1);

    // 2) gates
    gate_kernel<<<dim3(8, BZ), 512>>>(1, q4v_w, q4v_b, 0);
    gate_kernel<<<dim3(8, BZ), 512>>>(0, v4q_w, v4q_b, 1);

    // 3) memory tokens
    memtok_kernel<<<dim3(8, BZ), 128>>>(m_v_k, m_v_v, m_c_k, m_c_v);

    // 4) trans GEMMs
    const float* xin[3]  = {v, q, c};
    const float* lw[3]   = {v_lin_w, q_lin_w, c_lin_w};
    const float* lb[3]   = {v_lin_b, q_lin_b, c_lin_b};
    const float* masks[3] = {v_mask, q_mask, c_mask};
    const int    gatedv[3] = {1, 1, 0};
    const int    rowoffv[3] = {1, 0, 1};

    uint32_t* qA = nullptr; cudaGetSymbolAddress((void**)&qA, g_qA);
    uint32_t* qB = nullptr; cudaGetSymbolAddress((void**)&qB, g_qB);

    dim3 tg(N3 / 128, (BZ * SEQ) / 128);
    for (int m = 0; m < 3; m++) {
        quant_kernel<<<NA / 1024, 256>>>(xin[m], qA, NA, 0);
        quantT_kernel<<<dim3(N3 / 32, DM / 32), dim3(32, 8)>>>(lw[m], qB, N3);
        gemm_cp<0><<<tg, 256, GEMM_SMEM>>>(lb[m], masks[m], nullptr, m,
                                           gatedv[m], rowoffv[m]);
    }

    // 5) per-modality fused flash attention + out projection
    const float* ows[3] = {v_out_w, q_out_w, c_out_w};
    const float* obs[3] = {v_out_b, q_out_b, c_out_b};
    const int    sks[3] = {SKM, SEQ, SKM};
    const int    hasm[3] = {1, 0, 1};

    dim3 og(DM / 128, (BZ * SEQ) / 128);
    for (int m = 0; m < 3; m++) {
        flash_attn<<<dim3(SEQ / 64, BZ * NH), 256, FA_SMEM>>>(masks[m], m, sks[m], hasm[m]);
        quant_kernel<<<NA / 1024, 256>>>(xin[m], qA, NA, 1);       // x + U
        quantT_kernel<<<dim3(DM / 32, DM / 32), dim3(32, 8)>>>(ows[m], qB, DM);
        gemm_cp<1><<<og, 256, GEMM_SMEM>>>(obs[m], nullptr,
                                           out + (size_t)m * BZ * SEQ * DM,
                                           0, 0, 0);
    }
}

// round 16
// speedup vs baseline: 2.5504x; 1.1221x over previous
#include <cuda_runtime.h>
#include <cuda_fp16.h>
#include <math.h>
#include <stdint.h>

#define BZ   16
#define SEQ  512
#define DM   1024
#define NH   8
#define DH   128
#define SKM  513          // keys with memory token
#define N3   3072
#define NA   (BZ * SEQ * DM)

// ---------------- static scratch (device globals; allocation-free) ----------
__device__ float g_mean[2][BZ][DM];
__device__ float g_gate[2][BZ][DM];
__device__ __half g_Kh[3][BZ][SEQ + 1][DM];
__device__ __half g_Qh[3][BZ][SEQ][DM];
__device__ __half g_Vh[3][BZ][SEQ + 1][DM];
__device__ uint32_t g_qA[3 * NA / 2];          // fp16 pairs, per-modality A operand
__device__ uint32_t g_qB[3 * N3 * DM / 2];     // fp16 pairs, per-modality W^T

__device__ __forceinline__ void mma_f16(float* c, uint32_t a0, uint32_t a1,
                                        uint32_t a2, uint32_t a3,
                                        uint32_t b0, uint32_t b1) {
    asm volatile(
        "mma.sync.aligned.m16n8k16.row.col.f32.f16.f16.f32 "
        "{%0,%1,%2,%3}, {%4,%5,%6,%7}, {%8,%9}, {%0,%1,%2,%3};"
        : "+f"(c[0]), "+f"(c[1]), "+f"(c[2]), "+f"(c[3])
        : "r"(a0), "r"(a1), "r"(a2), "r"(a3), "r"(b0), "r"(b1));
}
__device__ __forceinline__ void ldsm4(uint32_t& r0, uint32_t& r1, uint32_t& r2,
                                      uint32_t& r3, uint32_t addr) {
    asm volatile("ldmatrix.sync.aligned.m8n8.x4.shared.b16 {%0,%1,%2,%3}, [%4];"
                 : "=r"(r0), "=r"(r1), "=r"(r2), "=r"(r3) : "r"(addr));
}
__device__ __forceinline__ void ldsm4t(uint32_t& r0, uint32_t& r1, uint32_t& r2,
                                       uint32_t& r3, uint32_t addr) {
    asm volatile("ldmatrix.sync.aligned.m8n8.x4.trans.shared.b16 {%0,%1,%2,%3}, [%4];"
                 : "=r"(r0), "=r"(r1), "=r"(r2), "=r"(r3) : "r"(addr));
}
__device__ __forceinline__ uint32_t cvta_sm(const void* p) {
    uint32_t a;
    asm("{ .reg .u64 t; cvta.to.shared.u64 t, %1; cvt.u32.u64 %0, t; }" : "=r"(a) : "l"(p));
    return a;
}
__device__ __forceinline__ uint32_t packh2(float a, float b) {
    __half2 h = __floats2half2_rn(a, b);
    return *(uint32_t*)&h;
}

// ---------------- merged relu-quant for 3 inputs ----------------
__global__ void quantA3(const float* __restrict__ x0, const float* __restrict__ x1,
                        const float* __restrict__ x2) {
    int z = blockIdx.z;
    const float* x = (z == 0) ? x0 : (z == 1) ? x1 : x2;
    uint32_t* o = g_qA + (size_t)z * (NA / 2);
    int i = (blockIdx.x * 256 + threadIdx.x) * 4;
    float4 v = *(const float4*)(x + i);
    v.x = fmaxf(v.x, 0.f); v.y = fmaxf(v.y, 0.f);
    v.z = fmaxf(v.z, 0.f); v.w = fmaxf(v.w, 0.f);
    *(uint2*)(o + i / 2) = make_uint2(packh2(v.x, v.y), packh2(v.z, v.w));
}

// ------- merged transposed quant for 3 weights: [1024][N] -> [N][1024] ------
__global__ void quantT3(const float* __restrict__ w0, const float* __restrict__ w1,
                        const float* __restrict__ w2, int N) {
    __shared__ float t[32][33];
    int z = blockIdx.z;
    const float* w = (z == 0) ? w0 : (z == 1) ? w1 : w2;
    uint32_t* o = g_qB + (size_t)z * N * DM / 2;
    int n0 = blockIdx.x * 32, k0 = blockIdx.y * 32;
    int tx = threadIdx.x, ty = threadIdx.y;
#pragma unroll
    for (int r = 0; r < 4; r++) {
        int k = ty + r * 8;
        t[tx][k] = w[(size_t)(k0 + k) * N + n0 + tx];
    }
    __syncthreads();
    int idx = ty * 32 + tx;
#pragma unroll
    for (int r = 0; r < 2; r++) {
        int e = idx + r * 256;
        int n = e >> 4;
        int kp = (e & 15) * 2;
        o[((size_t)(n0 + n) * DM + k0 + kp) / 2] = packh2(t[n][kp], t[n][kp + 1]);
    }
}

// ============ cp.async 3-stage fp16 GEMM: 128x128x64 tile, 256 thr =========
// z = modality. MODE 0: trans (Ntot=N3), scatter to g_Kh/Qh/Vh with mask/gate.
// MODE 1: outproj (Ntot=DM) -> outp + z*NA.
#define LDH 72
#define GT_BYTES (128 * LDH * 2)
#define ST_BYTES (2 * GT_BYTES)
#define GEMM_SMEM (3 * ST_BYTES)
#define NKT 16

template <int MODE>
__global__ void __launch_bounds__(256, 2) gemm_cp(
    const float* __restrict__ bias0, const float* __restrict__ bias1,
    const float* __restrict__ bias2,
    const float* __restrict__ mask0, const float* __restrict__ mask1,
    const float* __restrict__ mask2,
    float* __restrict__ outp) {
    extern __shared__ __half smh[];
    uint32_t sbase = cvta_sm(smh);

    int z = blockIdx.z;
    const float* bias = (z == 0) ? bias0 : (z == 1) ? bias1 : bias2;
    const float* mask = (z == 0) ? mask0 : (z == 1) ? mask1 : mask2;
    const int Ntot = (MODE == 0) ? N3 : DM;
    const int gated = (MODE == 0) ? (z < 2 ? 1 : 0) : 0;
    const int rowoff = (MODE == 0) ? (z == 1 ? 0 : 1) : 0;

    int tid = threadIdx.x;
    int wid = tid >> 5, lane = tid & 31;
    int g = lane >> 2, u = lane & 3;
    int wm = (wid >> 2) * 64;
    int wn = (wid & 3) * 32;
    int mtile = blockIdx.y * 128;
    int ntile = blockIdx.x * 128;

    int mi = lane >> 3, r8 = lane & 7;
    uint32_t lmA = (uint32_t)(((mi & 1) * 8 + r8) * LDH * 2 + (mi >> 1) * 16);
    uint32_t lmB = (uint32_t)(((mi >> 1) * 8 + r8) * LDH * 2 + (mi & 1) * 16);

    int rows_[4], ch_[4];
    uint32_t aoff[4], boff[4];
#pragma unroll
    for (int l = 0; l < 4; l++) {
        int idx = tid + l * 256;
        rows_[l] = idx >> 3;
        ch_[l] = (idx & 7) * 8;
        aoff[l] = (uint32_t)(rows_[l] * LDH + ch_[l]) * 2;
        boff[l] = aoff[l] + GT_BYTES;
    }

    float acc[4][4][4];
#pragma unroll
    for (int i = 0; i < 4; i++)
#pragma unroll
        for (int j = 0; j < 4; j++)
#pragma unroll
            for (int e = 0; e < 4; e++) acc[i][j][e] = 0.f;

    const __half* Aq = (const __half*)g_qA + (size_t)z * NA;
    const __half* Bq = (const __half*)g_qB + (size_t)z * Ntot * DM;

#define ISSUE_TILE(KT, S) do {                                                     \
    if ((KT) < NKT) {                                                              \
        int _k0 = (KT) * 64;                                                       \
        uint32_t _sb = sbase + (uint32_t)(S) * ST_BYTES;                           \
        _Pragma("unroll")                                                          \
        for (int _l = 0; _l < 4; _l++) {                                           \
            const __half* _ga = Aq + (size_t)(mtile + rows_[_l]) * DM + _k0 + ch_[_l]; \
            asm volatile("cp.async.cg.shared.global [%0], [%1], 16;"               \
                         :: "r"(_sb + aoff[_l]), "l"(_ga) : "memory");             \
            const __half* _gb = Bq + (size_t)(ntile + rows_[_l]) * DM + _k0 + ch_[_l]; \
            asm volatile("cp.async.cg.shared.global [%0], [%1], 16;"               \
                         :: "r"(_sb + boff[_l]), "l"(_gb) : "memory");             \
        }                                                                          \
    }                                                                              \
    asm volatile("cp.async.commit_group;" ::: "memory");                           \
} while (0)

    ISSUE_TILE(0, 0);
    ISSUE_TILE(1, 1);
    asm volatile("cp.async.wait_group 1;" ::: "memory");
    __syncthreads();

    int cur = 0;
    for (int kt = 0; kt < NKT; kt++) {
        uint32_t stage = sbase + (uint32_t)cur * ST_BYTES;
        uint32_t aT = stage + (uint32_t)(wm * LDH) * 2 + lmA;
        uint32_t bT = stage + GT_BYTES + (uint32_t)(wn * LDH) * 2 + lmB;

#pragma unroll
        for (int ks = 0; ks < 4; ks++) {
            uint32_t kb = (uint32_t)(ks * 16) * 2;
            uint32_t af[4][4], bf[4][2];
#pragma unroll
            for (int i = 0; i < 4; i++)
                ldsm4(af[i][0], af[i][1], af[i][2], af[i][3],
                      aT + (uint32_t)(i * 16 * LDH) * 2 + kb);
#pragma unroll
            for (int jp = 0; jp < 2; jp++)
                ldsm4(bf[2 * jp][0], bf[2 * jp][1], bf[2 * jp + 1][0], bf[2 * jp + 1][1],
                      bT + (uint32_t)(jp * 16 * LDH) * 2 + kb);
#pragma unroll
            for (int i = 0; i < 4; i++)
#pragma unroll
                for (int j = 0; j < 4; j++)
                    mma_f16(acc[i][j], af[i][0], af[i][1], af[i][2], af[i][3],
                            bf[j][0], bf[j][1]);
        }

        int nxt = cur + 2; if (nxt >= 3) nxt -= 3;
        ISSUE_TILE(kt + 2, nxt);
        asm volatile("cp.async.wait_group 1;" ::: "memory");
        __syncthreads();
        cur = cur + 1; if (cur == 3) cur = 0;
    }

    // ---- epilogue ----
    int part = ntile >> 10;
#pragma unroll
    for (int i = 0; i < 4; i++) {
        int r0 = mtile + wm + i * 16 + g;
        int r1 = r0 + 8;
#pragma unroll
        for (int j = 0; j < 4; j++) {
            int col = ntile + wn + j * 8 + u * 2;
            if (MODE == 1) {
                float b0 = bias[col], b1 = bias[col + 1];
                float* op = outp + (size_t)z * NA;
                *(float2*)(op + (size_t)r0 * DM + col) =
                    make_float2(acc[i][j][0] + b0, acc[i][j][1] + b1);
                *(float2*)(op + (size_t)r1 * DM + col) =
                    make_float2(acc[i][j][2] + b0, acc[i][j][3] + b1);
            } else {
                float b0 = bias[col], b1 = bias[col + 1];
                int d0 = col & 1023;
#pragma unroll
                for (int h = 0; h < 2; h++) {
                    int r = h ? r1 : r0;
                    int b = r >> 9, si = r & 511;
                    float mk = mask[r];
                    float v0 = (acc[i][j][h * 2 + 0] + b0) * mk;
                    float v1 = (acc[i][j][h * 2 + 1] + b1) * mk;
                    if (gated && part < 2) {
                        v0 *= g_gate[z][b][d0];
                        v1 *= g_gate[z][b][d0 + 1];
                    }
                    __half* dst;
                    if (part == 0)      dst = &g_Kh[z][b][rowoff + si][d0];
                    else if (part == 1) dst = &g_Qh[z][b][si][d0];
                    else                dst = &g_Vh[z][b][rowoff + si][d0];
                    *(uint32_t*)dst = packh2(v0, v1);
                }
            }
        }
    }
}

// ================= fused flash attention (fp16 mma), merged z ===============
// Epilogue writes h(x + O) straight into g_qA[z] (feeds outproj GEMM).
#define FA_LD  136
#define FA_LDP 72
#define FA_SMEM ((3 * 64 * FA_LD + 64 * FA_LDP) * 2 + (64 * 3 + 128 + 64) * 4)

__global__ void __launch_bounds__(256) flash_attn(
    const float* __restrict__ mask0, const float* __restrict__ mask1,
    const float* __restrict__ mask2,
    const float* __restrict__ x0, const float* __restrict__ x1,
    const float* __restrict__ x2) {
    extern __shared__ char smraw[];
    __half* Qh = (__half*)smraw;
    __half* Kh = Qh + 64 * FA_LD;
    __half* Vh = Kh + 64 * FA_LD;
    __half* Ph = Vh + 64 * FA_LD;
    float* m_s  = (float*)(Ph + 64 * FA_LDP);
    float* l_s  = m_s + 64;
    float* al_s = l_s + 64;
    float* red  = al_s + 64;     // [2][64]
    float* kms  = red + 128;

    int z = blockIdx.z;
    const float* mask = (z == 0) ? mask0 : (z == 1) ? mask1 : mask2;
    const float* xg   = (z == 0) ? x0 : (z == 1) ? x1 : x2;
    int Sk = (z == 1) ? SEQ : SKM;
    int hasmem = (z != 1);

    int tid = threadIdx.x;
    int wid = tid >> 5, lane = tid & 31;
    int g = lane >> 2, u = lane & 3;
    int mi = lane >> 3, r8 = lane & 7;
    int wm = (wid >> 1) * 16;
    int wns = (wid & 1) * 32;
    int wno = (wid & 1) * 64;
    int bh = blockIdx.y;
    int b = bh >> 3, h = bh & 7;
    int qt0 = blockIdx.x * 64;

    const __half* Qg = &g_Qh[z][b][0][h * DH];
    const __half* Kg = &g_Kh[z][b][0][h * DH];
    const __half* Vg = &g_Vh[z][b][0][h * DH];

    uint32_t smQ = cvta_sm(Qh), smK = cvta_sm(Kh);
    uint32_t smV = cvta_sm(Vh), smP = cvta_sm(Ph);
    uint32_t lmA  = (uint32_t)(((mi & 1) * 8 + r8) * FA_LD * 2 + (mi >> 1) * 16);
    uint32_t lmB  = (uint32_t)(((mi >> 1) * 8 + r8) * FA_LD * 2 + (mi & 1) * 16);
    uint32_t lmAP = (uint32_t)(((mi & 1) * 8 + r8) * FA_LDP * 2 + (mi >> 1) * 16);
    uint32_t lmVT = (uint32_t)((lane & 15) * FA_LD * 2 + (lane >> 4) * 16);

    // load Q tile once
#pragma unroll
    for (int l = 0; l < 4; l++) {
        int idx = tid + l * 256;
        int row = idx >> 4;
        int c8 = (idx & 15) * 8;
        *(uint4*)&Qh[row * FA_LD + c8] =
            *(const uint4*)(Qg + (size_t)(qt0 + row) * DM + c8);
    }
    if (tid < 64) { m_s[tid] = -3.4e38f; l_s[tid] = 0.f; }

    float acc_o[8][4];
#pragma unroll
    for (int j = 0; j < 8; j++)
#pragma unroll
        for (int e = 0; e < 4; e++) acc_o[j][e] = 0.f;

    const float scl = 0.08838834764831845f;   // 1/sqrt(128)
    int r0l = wm + g, r1l = wm + g + 8;
    int nt = (Sk + 63) >> 6;

    for (int t = 0; t < nt; t++) {
        int kt0 = t * 64;
        __syncthreads();   // A
#pragma unroll
        for (int l = 0; l < 4; l++) {
            int idx = tid + l * 256;
            int row = idx >> 4;
            int c8 = (idx & 15) * 8;
            int key = kt0 + row;
            uint4 kv = make_uint4(0, 0, 0, 0), vv = make_uint4(0, 0, 0, 0);
            if (key < Sk) {
                kv = *(const uint4*)(Kg + (size_t)key * DM + c8);
                vv = *(const uint4*)(Vg + (size_t)key * DM + c8);
            }
            *(uint4*)&Kh[row * FA_LD + c8] = kv;
            *(uint4*)&Vh[row * FA_LD + c8] = vv;
        }
        if (tid < 64) {
            int key = kt0 + tid;
            float km = 0.f;
            if (key < Sk)
                km = hasmem ? ((key == 0) ? 1.f : mask[b * SEQ + key - 1])
                            : mask[b * SEQ + key];
            kms[tid] = km;
        }
        __syncthreads();   // B

        float s[4][4];
#pragma unroll
        for (int j = 0; j < 4; j++)
#pragma unroll
            for (int e = 0; e < 4; e++) s[j][e] = 0.f;
        uint32_t aQ = smQ + (uint32_t)(wm * FA_LD) * 2 + lmA;
        uint32_t bK = smK + (uint32_t)(wns * FA_LD) * 2 + lmB;
#pragma unroll
        for (int ks = 0; ks < 8; ks++) {
            uint32_t kb = (uint32_t)(ks * 16) * 2;
            uint32_t a0, a1, a2, a3;
            uint32_t bf[4][2];
            ldsm4(a0, a1, a2, a3, aQ + kb);
#pragma unroll
            for (int jp = 0; jp < 2; jp++)
                ldsm4(bf[2 * jp][0], bf[2 * jp][1], bf[2 * jp + 1][0], bf[2 * jp + 1][1],
                      bK + (uint32_t)(jp * 16 * FA_LD) * 2 + kb);
#pragma unroll
            for (int j = 0; j < 4; j++)
                mma_f16(s[j], a0, a1, a2, a3, bf[j][0], bf[j][1]);
        }

        float rm0 = -3.4e38f, rm1 = -3.4e38f;
#pragma unroll
        for (int j = 0; j < 4; j++) {
            int col = wns + j * 8 + u * 2;
            float k0m = kms[col], k1m = kms[col + 1];
            s[j][0] = (k0m != 0.f ? s[j][0] : -1e9f) * scl;
            s[j][1] = (k1m != 0.f ? s[j][1] : -1e9f) * scl;
            s[j][2] = (k0m != 0.f ? s[j][2] : -1e9f) * scl;
            s[j][3] = (k1m != 0.f ? s[j][3] : -1e9f) * scl;
            rm0 = fmaxf(rm0, fmaxf(s[j][0], s[j][1]));
            rm1 = fmaxf(rm1, fmaxf(s[j][2], s[j][3]));
        }
        rm0 = fmaxf(rm0, __shfl_xor_sync(0xffffffffu, rm0, 1));
        rm0 = fmaxf(rm0, __shfl_xor_sync(0xffffffffu, rm0, 2));
        rm1 = fmaxf(rm1, __shfl_xor_sync(0xffffffffu, rm1, 1));
        rm1 = fmaxf(rm1, __shfl_xor_sync(0xffffffffu, rm1, 2));
        if (u == 0) {
            red[(wid & 1) * 64 + r0l] = rm0;
            red[(wid & 1) * 64 + r1l] = rm1;
        }
        __syncthreads();   // C
        if ((wid & 1) == 0 && u == 0) {
#pragma unroll
            for (int hh = 0; hh < 2; hh++) {
                int r = hh ? r1l : r0l;
                float tm = fmaxf(red[r], red[64 + r]);
                float mo = m_s[r];
                float mn = fmaxf(mo, tm);
                al_s[r] = expf(mo - mn);
                m_s[r] = mn;
            }
        }
        __syncthreads();   // D
        float mn0 = m_s[r0l], mn1 = m_s[r1l];
        float rs0 = 0.f, rs1 = 0.f;
        uint32_t* Ph32 = (uint32_t*)Ph;
#pragma unroll
        for (int j = 0; j < 4; j++) {
            int col = wns + j * 8 + u * 2;
            float p0 = expf(s[j][0] - mn0);
            float p1 = expf(s[j][1] - mn0);
            float p2 = expf(s[j][2] - mn1);
            float p3 = expf(s[j][3] - mn1);
            rs0 += p0 + p1; rs1 += p2 + p3;
            Ph32[(r0l * FA_LDP + col) >> 1] = packh2(p0, p1);
            Ph32[(r1l * FA_LDP + col) >> 1] = packh2(p2, p3);
        }
        rs0 += __shfl_xor_sync(0xffffffffu, rs0, 1);
        rs0 += __shfl_xor_sync(0xffffffffu, rs0, 2);
        rs1 += __shfl_xor_sync(0xffffffffu, rs1, 1);
        rs1 += __shfl_xor_sync(0xffffffffu, rs1, 2);
        if (u == 0) {
            red[(wid & 1) * 64 + r0l] = rs0;
            red[(wid & 1) * 64 + r1l] = rs1;
        }
        __syncthreads();   // E
        if ((wid & 1) == 0 && u == 0) {
            l_s[r0l] = l_s[r0l] * al_s[r0l] + red[r0l] + red[64 + r0l];
            l_s[r1l] = l_s[r1l] * al_s[r1l] + red[r1l] + red[64 + r1l];
        }
        float a0s = al_s[r0l], a1s = al_s[r1l];
#pragma unroll
        for (int j = 0; j < 8; j++) {
            acc_o[j][0] *= a0s; acc_o[j][1] *= a0s;
            acc_o[j][2] *= a1s; acc_o[j][3] *= a1s;
        }
        uint32_t aP = smP + (uint32_t)(wm * FA_LDP) * 2 + lmAP;
#pragma unroll
        for (int ks = 0; ks < 4; ks++) {
            uint32_t kb = (uint32_t)(ks * 16) * 2;
            uint32_t a0, a1, a2, a3;
            uint32_t bf[8][2];
            ldsm4(a0, a1, a2, a3, aP + kb);
            uint32_t vbase = smV + (uint32_t)(ks * 16 * FA_LD) * 2 +
                             (uint32_t)(wno * 2) + lmVT;
#pragma unroll
            for (int jp = 0; jp < 4; jp++)
                ldsm4t(bf[2 * jp][0], bf[2 * jp][1], bf[2 * jp + 1][0], bf[2 * jp + 1][1],
                       vbase + (uint32_t)(jp * 16) * 2);
#pragma unroll
            for (int j = 0; j < 8; j++)
                mma_f16(acc_o[j], a0, a1, a2, a3, bf[j][0], bf[j][1]);
        }
    }
    __syncthreads();
    float inv0 = 1.f / l_s[r0l];
    float inv1 = 1.f / l_s[r1l];
    int qr0 = qt0 + r0l, qr1 = qt0 + r1l;
    uint32_t* qAo = g_qA + (size_t)z * (NA / 2);
#pragma unroll
    for (int j = 0; j < 8; j++) {
        int col = h * DH + wno + j * 8 + u * 2;
        size_t o0 = ((size_t)(b * SEQ + qr0) * DM + col);
        size_t o1 = ((size_t)(b * SEQ + qr1) * DM + col);
        float2 xv0 = *(const float2*)(xg + o0);
        float2 xv1 = *(const float2*)(xg + o1);
        qAo[o0 >> 1] = packh2(xv0.x + acc_o[j][0] * inv0, xv0.y + acc_o[j][1] * inv0);
        qAo[o1 >> 1] = packh2(xv1.x + acc_o[j][2] * inv1, xv1.y + acc_o[j][3] * inv1);
    }
}

// ---------------- merged masked mean (z = slot) ----------------
__global__ void mean_kernel(const float* __restrict__ x0, const float* __restrict__ x1,
                            const float* __restrict__ mk0, const float* __restrict__ mk1) {
    int z = blockIdx.z;
    const float* x = z ? x1 : x0;
    const float* mask = z ? mk1 : mk0;
    int b = blockIdx.y;
    int d = blockIdx.x * 128 + threadIdx.x;
    __shared__ float sm[SEQ];
    __shared__ float smsum;
    for (int i = threadIdx.x; i < SEQ; i += 128) sm[i] = mask[b * SEQ + i];
    __syncthreads();
    if (threadIdx.x == 0) {
        float s = 0.f;
        for (int i = 0; i < SEQ; i++) s += sm[i];
        smsum = s;
    }
    __syncthreads();
    float inv = 1.f / smsum;
    float acc = 0.f;
    for (int i = 0; i < SEQ; i++) acc += x[(size_t)(b * SEQ + i) * DM + d] * sm[i];
    g_mean[z][b][d] = acc * inv;
}

// -------- merged gate (z=0: mean1->gate0 w/q4v; z=1: mean0->gate1 w/v4q) ----
__global__ void __launch_bounds__(512) gate_kernel(
    const float* __restrict__ w0, const float* __restrict__ b0,
    const float* __restrict__ w1, const float* __restrict__ b1) {
    int z = blockIdx.z;
    const float* w = z ? w1 : w0;
    const float* bias = z ? b1 : b0;
    int mean_slot = z ? 0 : 1;
    int b = blockIdx.y;
    int tx = threadIdx.x;
    int dl = tx & 127, kg = tx >> 7;
    int d = blockIdx.x * 128 + dl;
    __shared__ float sm[DM];
    __shared__ float part[4][128];
    for (int k = tx; k < DM; k += 512) sm[k] = fmaxf(g_mean[mean_slot][b][k], 0.f);
    __syncthreads();
    float acc = 0.f;
    int k0 = kg * 256;
    for (int k = k0; k < k0 + 256; k++) acc = fmaf(sm[k], w[(size_t)k * DM + d], acc);
    part[kg][dl] = acc;
    __syncthreads();
    if (kg == 0) {
        float s = part[0][dl] + part[1][dl] + part[2][dl] + part[3][dl] + bias[d];
        g_gate[z][b][d] = 1.f + 1.f / (1.f + expf(-s));
    }
}

// ---------------- memory tokens (fp16 K/V row 0) ----------------
__global__ void memtok_kernel(const float* __restrict__ mvk, const float* __restrict__ mvv,
                              const float* __restrict__ mck, const float* __restrict__ mcv) {
    int b = blockIdx.y;
    int d = blockIdx.x * 128 + threadIdx.x;
    float gv = g_gate[0][b][d];
    g_Kh[0][b][0][d] = __float2half(32.f * mvk[d] * gv);
    g_Vh[0][b][0][d] = __float2half(mvv[d]);
    g_Kh[2][b][0][d] = __float2half(32.f * mck[d]);
    g_Vh[2][b][0][d] = __float2half(mcv[d]);
}

// ---------------- orchestration ----------------
extern "C" void kernel_launch(void* const* d_in, const int* in_sizes, int n_in,
                              void* d_out, int out_size) {
    const float* v      = (const float*)d_in[0];
    const float* q      = (const float*)d_in[1];
    const float* c      = (const float*)d_in[2];
    const float* v_mask = (const float*)d_in[3];
    const float* q_mask = (const float*)d_in[4];
    const float* c_mask = (const float*)d_in[5];
    const float* v4q_w  = (const float*)d_in[6];
    const float* v4q_b  = (const float*)d_in[7];
    const float* q4v_w  = (const float*)d_in[8];
    const float* q4v_b  = (const float*)d_in[9];
    const float* v_lin_w = (const float*)d_in[10];
    const float* v_lin_b = (const float*)d_in[11];
    const float* q_lin_w = (const float*)d_in[12];
    const float* q_lin_b = (const float*)d_in[13];
    const float* c_lin_w = (const float*)d_in[14];
    const float* c_lin_b = (const float*)d_in[15];
    const float* m_v_k  = (const float*)d_in[16];
    const float* m_v_v  = (const float*)d_in[17];
    const float* m_c_k  = (const float*)d_in[18];
    const float* m_c_v  = (const float*)d_in[19];
    const float* v_out_w = (const float*)d_in[20];
    const float* v_out_b = (const float*)d_in[21];
    const float* q_out_w = (const float*)d_in[22];
    const float* q_out_b = (const float*)d_in[23];
    const float* c_out_w = (const float*)d_in[24];
    const float* c_out_b = (const float*)d_in[25];
    float* out = (float*)d_out;

    static int attr_set = 0;
    if (!attr_set) {
        cudaFuncSetAttribute(flash_attn, cudaFuncAttributeMaxDynamicSharedMemorySize, FA_SMEM);
        cudaFuncSetAttribute(gemm_cp<0>, cudaFuncAttributeMaxDynamicSharedMemorySize, GEMM_SMEM);
        cudaFuncSetAttribute(gemm_cp<1>, cudaFuncAttributeMaxDynamicSharedMemorySize, GEMM_SMEM);
        attr_set = 1;
    }

    // 1) masked means (z=0: v, z=1: q)
    mean_kernel<<<dim3(8, BZ, 2), 128>>>(v, q, v_mask, q_mask);

    // 2) gates (z=0: gate0 from q_mean/q4v; z=1: gate1 from v_mean/v4q)
    gate_kernel<<<dim3(8, BZ, 2), 512>>>(q4v_w, q4v_b, v4q_w, v4q_b);

    // 3) memory tokens
    memtok_kernel<<<dim3(8, BZ), 128>>>(m_v_k, m_v_v, m_c_k, m_c_v);

    // 4) quantize inputs (relu) + trans weights, then merged trans GEMM
    quantA3<<<dim3(NA / 1024, 1, 3), 256>>>(v, q, c);
    quantT3<<<dim3(N3 / 32, DM / 32, 3), dim3(32, 8)>>>(v_lin_w, q_lin_w, c_lin_w, N3);
    gemm_cp<0><<<dim3(N3 / 128, (BZ * SEQ) / 128, 3), 256, GEMM_SMEM>>>(
        v_lin_b, q_lin_b, c_lin_b, v_mask, q_mask, c_mask, nullptr);

    // 5) merged flash attention (writes h(x+U) into g_qA)
    flash_attn<<<dim3(SEQ / 64, BZ * NH, 3), 256, FA_SMEM>>>(
        v_mask, q_mask, c_mask, v, q, c);

    // 6) quantize out-proj weights, merged outproj GEMM
    quantT3<<<dim3(DM / 32, DM / 32, 3), dim3(32, 8)>>>(v_out_w, q_out_w, c_out_w, DM);
    gemm_cp<1><<<dim3(DM / 128, (BZ * SEQ) / 128, 3), 256, GEMM_SMEM>>>(
        v_out_b, q_out_b, c_out_b, nullptr, nullptr, nullptr, out);
}